// round 3
// baseline (speedup 1.0000x reference)
#include <cuda_runtime.h>
#include <cstdint>
#include <cstddef>

#define NN 100000
#define MAXE 3300000   // 3.2M edges + 100k self loops

// ---------------- scratch (device globals; no allocation allowed) ----------
__device__ int   g_deg[NN];
__device__ float g_dinv[NN];
__device__ int   g_rowptr[NN + 1];
__device__ int   g_cursor[NN];
__device__ int   g_col[MAXE];
__device__ __align__(16) float g_bufA[(size_t)NN * 1024];
__device__ __align__(16) float g_bufB[(size_t)NN * 1024];

// Device-side buffer resolution: NO host-side symbol APIs anywhere.
// sel: 0 -> g_bufA, 1 -> g_bufB, else -> use the passed pointer.
__device__ __forceinline__ const float* rbuf(const float* p, int sel) {
    if (sel == 0) return g_bufA;
    if (sel == 1) return g_bufB;
    return p;
}
__device__ __forceinline__ float* wbuf(float* p, int sel) {
    if (sel == 0) return g_bufA;
    if (sel == 1) return g_bufB;
    return p;
}

// ---------------- CSR construction ----------------
// edge_index is int32 (JAX default x64-disabled downgrades int64 -> int32):
// layout [2, E] row-major: src = ei[0..E), dst = ei[E..2E).

__global__ void k_init_deg() {
    int v = blockIdx.x * blockDim.x + threadIdx.x;
    if (v < NN) g_deg[v] = 1;  // self loop
}

__global__ void k_count(const int* __restrict__ ei, int E) {
    int i = blockIdx.x * blockDim.x + threadIdx.x;
    if (i < E) {
        int d = ei[E + i];
        if ((unsigned)d < NN) atomicAdd(&g_deg[d], 1);
    }
}

// single-block chunked Hillis-Steele scan over 100k degrees
__global__ void k_scan() {
    __shared__ int s[1024];
    int tid = threadIdx.x;
    int carry = 0;
    if (tid == 0) g_rowptr[0] = 0;
    for (int base = 0; base < NN; base += 1024) {
        int idx = base + tid;
        int v = (idx < NN) ? g_deg[idx] : 0;
        __syncthreads();          // protect s from previous-iteration reads
        s[tid] = v;
        __syncthreads();
        for (int off = 1; off < 1024; off <<= 1) {
            int t = (tid >= off) ? s[tid - off] : 0;
            __syncthreads();
            s[tid] += t;
            __syncthreads();
        }
        int incl = s[tid];
        if (idx < NN) {
            g_rowptr[idx + 1] = carry + incl;
            g_cursor[idx]     = carry + incl - v;   // exclusive prefix
        }
        carry += s[1023];
        __syncthreads();
    }
}

__global__ void k_node_prep() {   // dinv + self-loop fill
    int v = blockIdx.x * blockDim.x + threadIdx.x;
    if (v < NN) {
        g_dinv[v] = rsqrtf((float)g_deg[v]);
        int pos = atomicAdd(&g_cursor[v], 1);
        if ((unsigned)pos < MAXE) g_col[pos] = v;
    }
}

__global__ void k_fill_edges(const int* __restrict__ ei, int E) {
    int i = blockIdx.x * blockDim.x + threadIdx.x;
    if (i < E) {
        int srcv = ei[i];
        int dstv = ei[E + i];
        if ((unsigned)srcv < NN && (unsigned)dstv < NN) {
            int pos = atomicAdd(&g_cursor[dstv], 1);
            if ((unsigned)pos < MAXE) g_col[pos] = srcv;
        }
    }
}

// ---------------- aggregation: out[v] = dinv[v] * sum_u dinv[u] * in[u] ----

// block-per-node, F >= 256
template <int F, bool RELU, bool BIAS>
__global__ void agg_block_kernel(const float* inp, int insel,
                                 float* outp, int outsel,
                                 const float* __restrict__ bias) {
    constexpr int TPB = 256;
    constexpr int CPT = F / TPB;
    const float* in  = rbuf(inp, insel);
    float*       out = wbuf(outp, outsel);
    int v = blockIdx.x;
    int tid = threadIdx.x;
    float acc[CPT];
#pragma unroll
    for (int j = 0; j < CPT; ++j) acc[j] = 0.0f;
    int s = g_rowptr[v], e = g_rowptr[v + 1];
    for (int p = s; p < e; ++p) {
        int u = g_col[p];
        float du = g_dinv[u];
        const float* row = in + (size_t)u * F;
#pragma unroll
        for (int j = 0; j < CPT; ++j)
            acc[j] = fmaf(du, row[tid + j * TPB], acc[j]);
    }
    float dv = g_dinv[v];
    float* orow = out + (size_t)v * F;
#pragma unroll
    for (int j = 0; j < CPT; ++j) {
        float val = acc[j] * dv;
        if (BIAS) val += bias[tid + j * TPB];
        if (RELU) val = fmaxf(val, 0.0f);
        orow[tid + j * TPB] = val;
    }
}

// warp-per-node, F <= 32
template <int F, bool RELU, bool BIAS>
__global__ void agg_warp_kernel(const float* inp, int insel,
                                float* outp, int outsel,
                                const float* __restrict__ bias) {
    const float* in  = rbuf(inp, insel);
    float*       out = wbuf(outp, outsel);
    int gt = blockIdx.x * blockDim.x + threadIdx.x;
    int v = gt >> 5;
    int lane = gt & 31;
    if (v >= NN || lane >= F) return;
    float acc = 0.0f;
    int s = g_rowptr[v], e = g_rowptr[v + 1];
    for (int p = s; p < e; ++p) {
        int u = g_col[p];
        acc = fmaf(g_dinv[u], in[(size_t)u * F + lane], acc);
    }
    float val = acc * g_dinv[v];
    if (BIAS) val += bias[lane];
    if (RELU) val = fmaxf(val, 0.0f);
    out[(size_t)v * F + lane] = val;
}

// ---------------- SGEMM: C[M,N] = A[M,K] @ W[K,N] (+bias)(+relu) ----------
// BM=128, BN=64, BK=16, 256 threads, each thread computes 8x4.

template <bool RELU, bool BIAS>
__global__ __launch_bounds__(256)
void sgemm_kernel(const float* Ap, int asel,
                  const float* __restrict__ W,
                  const float* __restrict__ bias,
                  float* Cp, int csel,
                  int M, int K, int Nc) {
    __shared__ float As[16][132];   // [k][m], padded (132*4B = 528 = 33*16: aligned)
    __shared__ float Bs[16][64];    // [k][n]
    const float* A = rbuf(Ap, asel);
    float*       C = wbuf(Cp, csel);
    const int tid = threadIdx.x;
    const int bm = blockIdx.x * 128;
    const int bn = blockIdx.y * 64;
    const int tx = tid & 15;        // n dir
    const int ty = tid >> 4;        // m dir
    float acc[8][4];
#pragma unroll
    for (int i = 0; i < 8; ++i)
#pragma unroll
        for (int j = 0; j < 4; ++j) acc[i][j] = 0.0f;

    const int ar = tid >> 2;          // 0..63
    const int ac = (tid & 3) * 4;     // 0,4,8,12
    const int wr = tid >> 4;          // 0..15
    const int wc = (tid & 15) * 4;    // 0..60

    for (int k0 = 0; k0 < K; k0 += 16) {
        // A tile: 128 x 16 (two rows of float4 per thread), store transposed
#pragma unroll
        for (int h = 0; h < 2; ++h) {
            int r = ar + h * 64;
            int gr = bm + r;
            float4 av = make_float4(0.f, 0.f, 0.f, 0.f);
            if (gr < M) av = *(const float4*)(A + (size_t)gr * K + k0 + ac);
            As[ac + 0][r] = av.x;
            As[ac + 1][r] = av.y;
            As[ac + 2][r] = av.z;
            As[ac + 3][r] = av.w;
        }
        // W tile: 16 x 64, one float4 per thread
        *(float4*)(&Bs[wr][wc]) =
            *(const float4*)(W + (size_t)(k0 + wr) * Nc + bn + wc);
        __syncthreads();
#pragma unroll
        for (int k = 0; k < 16; ++k) {
            float a0[8], b0[4];
            *(float4*)(a0)     = *(const float4*)(&As[k][ty * 8]);
            *(float4*)(a0 + 4) = *(const float4*)(&As[k][ty * 8 + 4]);
            *(float4*)(b0)     = *(const float4*)(&Bs[k][tx * 4]);
#pragma unroll
            for (int i = 0; i < 8; ++i)
#pragma unroll
                for (int j = 0; j < 4; ++j)
                    acc[i][j] = fmaf(a0[i], b0[j], acc[i][j]);
        }
        __syncthreads();
    }

#pragma unroll
    for (int i = 0; i < 8; ++i) {
        int gr = bm + ty * 8 + i;
        if (gr < M) {
#pragma unroll
            for (int j = 0; j < 4; ++j) {
                float v = acc[i][j];
                if (BIAS) v += bias[bn + tx * 4 + j];
                if (RELU) v = fmaxf(v, 0.0f);
                C[(size_t)gr * Nc + bn + tx * 4 + j] = v;
            }
        }
    }
}

// ---------------- tiny GEMM for final layer: [NN,256] @ [256,6] ----------
// reads g_bufB, writes g_bufA (row stride 6)
__global__ void gemm6_kernel(const float* __restrict__ W) {
    const float* A = g_bufB;
    float*       C = g_bufA;
    int gt = blockIdx.x * blockDim.x + threadIdx.x;
    int row = gt >> 5;
    int lane = gt & 31;
    if (row >= NN) return;
    float acc[6] = {0.f, 0.f, 0.f, 0.f, 0.f, 0.f};
    const float* a = A + (size_t)row * 256;
    for (int k = lane; k < 256; k += 32) {
        float av = a[k];
        const float* wr = W + k * 6;
#pragma unroll
        for (int j = 0; j < 6; ++j) acc[j] = fmaf(av, wr[j], acc[j]);
    }
#pragma unroll
    for (int j = 0; j < 6; ++j)
#pragma unroll
        for (int off = 16; off > 0; off >>= 1)
            acc[j] += __shfl_xor_sync(0xFFFFFFFFu, acc[j], off);
    if (lane < 6) C[(size_t)row * 6 + lane] = acc[lane];
}

// ---------------- host: full pipeline (graph-capturable; launches only) ----

extern "C" void kernel_launch(void* const* d_in, const int* in_sizes, int n_in,
                              void* d_out, int out_size) {
    const float* x  = (const float*)d_in[0];
    const int*   ei = (const int*)d_in[1];    // int32 (JAX x64-disabled)
    const float* W1 = (const float*)d_in[2];
    const float* b1 = (const float*)d_in[3];
    const float* W2 = (const float*)d_in[4];
    const float* b2 = (const float*)d_in[5];
    const float* W3 = (const float*)d_in[6];
    const float* b3 = (const float*)d_in[7];
    const float* W4 = (const float*)d_in[8];
    const float* b4 = (const float*)d_in[9];
    const float* W5 = (const float*)d_in[10];
    const float* b5 = (const float*)d_in[11];
    float* out = (float*)d_out;

    const int E = in_sizes[1] / 2;

    const int TPB = 256;
    const int gN = (NN + TPB - 1) / TPB;
    const int gE = (E + TPB - 1) / TPB;
    const int gWarp = ((NN * 32) + TPB - 1) / TPB;   // warp-per-node grids
    const int gM = (NN + 127) / 128;                 // 782

    // ---- CSR + norm ----
    k_init_deg<<<gN, TPB>>>();
    k_count<<<gE, TPB>>>(ei, E);
    k_scan<<<1, 1024>>>();
    k_node_prep<<<gN, TPB>>>();
    k_fill_edges<<<gE, TPB>>>(ei, E);

    // ---- Layer 1: agg(x) [F=32] -> GEMM 32x256 + b1 + relu ----
    agg_warp_kernel<32, false, false><<<gWarp, TPB>>>(x, -1, nullptr, 0, nullptr);
    sgemm_kernel<true, true><<<dim3(gM, 256 / 64), TPB>>>(nullptr, 0, W1, b1, nullptr, 1, NN, 32, 256);

    // ---- Layer 2: agg [F=256] -> GEMM 256x1024 + b2 + relu ----
    agg_block_kernel<256, false, false><<<NN, TPB>>>(nullptr, 1, nullptr, 0, nullptr);
    sgemm_kernel<true, true><<<dim3(gM, 1024 / 64), TPB>>>(nullptr, 0, W2, b2, nullptr, 1, NN, 256, 1024);

    // ---- Layer 3: agg [F=1024] -> GEMM 1024x1024 + b3 + relu ----
    agg_block_kernel<1024, false, false><<<NN, TPB>>>(nullptr, 1, nullptr, 0, nullptr);
    sgemm_kernel<true, true><<<dim3(gM, 1024 / 64), TPB>>>(nullptr, 0, W3, b3, nullptr, 1, NN, 1024, 1024);

    // ---- Layer 4: GEMM 1024x256 (no bias/relu) -> agg [F=256] + b4 + relu ----
    sgemm_kernel<false, false><<<dim3(gM, 256 / 64), TPB>>>(nullptr, 1, W4, nullptr, nullptr, 0, NN, 1024, 256);
    agg_block_kernel<256, true, true><<<NN, TPB>>>(nullptr, 0, nullptr, 1, b4);

    // ---- Layer 5: GEMM 256x6 -> agg [F=6] + b5 ----
    gemm6_kernel<<<gWarp, TPB>>>(W5);
    agg_warp_kernel<6, false, true><<<gWarp, TPB>>>(nullptr, 0, out, -1, b5);
}

// round 9
// speedup vs baseline: 1.2032x; 1.2032x over previous
#include <cuda_runtime.h>
#include <cuda_bf16.h>
#include <cstdint>
#include <cstddef>

#define NN 100000
#define MAXE 3300000

// ---------------- scratch ----------------
__device__ int   g_deg[NN];
__device__ float g_dinv[NN];
__device__ int   g_rowptr[NN + 1];
__device__ int   g_cursor[NN];
__device__ int   g_col[MAXE];
__device__ __align__(16) float g_bufA[(size_t)NN * 1024];
__device__ __align__(16) float g_bufB[(size_t)NN * 1024];

__device__ __forceinline__ const float* rbuf(const float* p, int sel) {
    if (sel == 0) return g_bufA;
    if (sel == 1) return g_bufB;
    return p;
}
__device__ __forceinline__ float* wbuf(float* p, int sel) {
    if (sel == 0) return g_bufA;
    if (sel == 1) return g_bufB;
    return p;
}

// ---------------- CSR construction ----------------
__global__ void k_init_deg() {
    int v = blockIdx.x * blockDim.x + threadIdx.x;
    if (v < NN) g_deg[v] = 1;
}
__global__ void k_count(const int* __restrict__ ei, int E) {
    int i = blockIdx.x * blockDim.x + threadIdx.x;
    if (i < E) {
        int d = ei[E + i];
        if ((unsigned)d < NN) atomicAdd(&g_deg[d], 1);
    }
}
__global__ void k_scan() {
    __shared__ int s[1024];
    int tid = threadIdx.x;
    int carry = 0;
    if (tid == 0) g_rowptr[0] = 0;
    for (int base = 0; base < NN; base += 1024) {
        int idx = base + tid;
        int v = (idx < NN) ? g_deg[idx] : 0;
        __syncthreads();
        s[tid] = v;
        __syncthreads();
        for (int off = 1; off < 1024; off <<= 1) {
            int t = (tid >= off) ? s[tid - off] : 0;
            __syncthreads();
            s[tid] += t;
            __syncthreads();
        }
        int incl = s[tid];
        if (idx < NN) {
            g_rowptr[idx + 1] = carry + incl;
            g_cursor[idx]     = carry + incl - v;
        }
        carry += s[1023];
        __syncthreads();
    }
}
__global__ void k_node_prep() {
    int v = blockIdx.x * blockDim.x + threadIdx.x;
    if (v < NN) {
        g_dinv[v] = rsqrtf((float)g_deg[v]);
        int pos = atomicAdd(&g_cursor[v], 1);
        if ((unsigned)pos < MAXE) g_col[pos] = v;
    }
}
__global__ void k_fill_edges(const int* __restrict__ ei, int E) {
    int i = blockIdx.x * blockDim.x + threadIdx.x;
    if (i < E) {
        int srcv = ei[i];
        int dstv = ei[E + i];
        if ((unsigned)srcv < NN && (unsigned)dstv < NN) {
            int pos = atomicAdd(&g_cursor[dstv], 1);
            if ((unsigned)pos < MAXE) g_col[pos] = srcv;
        }
    }
}

// ---------------- aggregation ----------------
template <int F, bool RELU, bool BIAS>
__global__ void agg_block_kernel(const float* inp, int insel,
                                 float* outp, int outsel,
                                 const float* __restrict__ bias) {
    constexpr int TPB = 256;
    constexpr int CPT = F / TPB;
    const float* in  = rbuf(inp, insel);
    float*       out = wbuf(outp, outsel);
    int v = blockIdx.x;
    int tid = threadIdx.x;
    float acc[CPT];
#pragma unroll
    for (int j = 0; j < CPT; ++j) acc[j] = 0.0f;
    int s = g_rowptr[v], e = g_rowptr[v + 1];
    for (int p = s; p < e; ++p) {
        int u = g_col[p];
        float du = g_dinv[u];
        const float* row = in + (size_t)u * F;
#pragma unroll
        for (int j = 0; j < CPT; ++j)
            acc[j] = fmaf(du, row[tid + j * TPB], acc[j]);
    }
    float dv = g_dinv[v];
    float* orow = out + (size_t)v * F;
#pragma unroll
    for (int j = 0; j < CPT; ++j) {
        float val = acc[j] * dv;
        if (BIAS) val += bias[tid + j * TPB];
        if (RELU) val = fmaxf(val, 0.0f);
        orow[tid + j * TPB] = val;
    }
}

template <int F, bool RELU, bool BIAS>
__global__ void agg_warp_kernel(const float* inp, int insel,
                                float* outp, int outsel,
                                const float* __restrict__ bias) {
    const float* in  = rbuf(inp, insel);
    float*       out = wbuf(outp, outsel);
    int gt = blockIdx.x * blockDim.x + threadIdx.x;
    int v = gt >> 5;
    int lane = gt & 31;
    if (v >= NN || lane >= F) return;
    float acc = 0.0f;
    int s = g_rowptr[v], e = g_rowptr[v + 1];
    for (int p = s; p < e; ++p) {
        int u = g_col[p];
        acc = fmaf(g_dinv[u], in[(size_t)u * F + lane], acc);
    }
    float val = acc * g_dinv[v];
    if (BIAS) val += bias[lane];
    if (RELU) val = fmaxf(val, 0.0f);
    out[(size_t)v * F + lane] = val;
}

// ================= mma.sync bf16 GEMM with 3-slot split =================
// C[M,Nc] = A[M,K] @ W[K,Nc] (+bias)(+relu), fp32 in/out.
// Split: x = hi + lo (both bf16). K expanded 3x:
//   A' slots per k: (hi_a, lo_a, hi_a); B' slots: (hi_b, hi_b, lo_b)
//   -> dot = hi*hi + lo*hi + hi*lo   (error ~2^-16)
// CTA tile 128x128, 8 warps each 64x32 of m16n8k16. Chunk = 16 orig k (48 k').
// Smem rows padded to stride 56 bf16 (112B): conflict-free u32 fragment loads.

#define GM_TPB 256
#define GM_STR 56                     // bf16 units per smem row
#define GM_TILE (128 * GM_STR)        // elements per tile buffer
#define GM_SMEM (4 * GM_TILE * 2)     // A0,A1,B0,B1 in bf16 bytes = 57344

__device__ __forceinline__ void mma16816(float* c, const uint32_t* a, const uint32_t* b) {
    asm volatile(
        "mma.sync.aligned.m16n8k16.row.col.f32.bf16.bf16.f32 "
        "{%0,%1,%2,%3}, {%4,%5,%6,%7}, {%8,%9}, {%0,%1,%2,%3};"
        : "+f"(c[0]), "+f"(c[1]), "+f"(c[2]), "+f"(c[3])
        : "r"(a[0]), "r"(a[1]), "r"(a[2]), "r"(a[3]), "r"(b[0]), "r"(b[1]));
}

__device__ __forceinline__ void ld_chunkA(const float* __restrict__ A, int M, int K,
                                          int bm, int k0, int tid, float* r) {
#pragma unroll
    for (int i = 0; i < 8; ++i) {
        int idx = tid + i * 256;
        int row = idx >> 4, kk = idx & 15;
        int gm = bm + row;
        r[i] = (gm < M) ? __ldg(A + (size_t)gm * K + k0 + kk) : 0.0f;
    }
}
__device__ __forceinline__ void st_chunkA(__nv_bfloat16* __restrict__ As,
                                          int tid, const float* r) {
#pragma unroll
    for (int i = 0; i < 8; ++i) {
        int idx = tid + i * 256;
        int row = idx >> 4, kk = idx & 15;
        float x = r[i];
        __nv_bfloat16 h = __float2bfloat16_rn(x);
        __nv_bfloat16 l = __float2bfloat16_rn(x - __bfloat162float(h));
        __nv_bfloat16* p = As + row * GM_STR + 3 * kk;
        p[0] = h; p[1] = l; p[2] = h;
    }
}
__device__ __forceinline__ void ld_chunkB(const float* __restrict__ W, int Nc,
                                          int bn, int k0, int tid, float* r) {
#pragma unroll
    for (int i = 0; i < 8; ++i) {
        int idx = tid + i * 256;
        int kk = idx >> 7, n = idx & 127;
        r[i] = __ldg(W + (size_t)(k0 + kk) * Nc + bn + n);
    }
}
__device__ __forceinline__ void st_chunkB(__nv_bfloat16* __restrict__ Bs,
                                          int tid, const float* r) {
#pragma unroll
    for (int i = 0; i < 8; ++i) {
        int idx = tid + i * 256;
        int kk = idx >> 7, n = idx & 127;
        float x = r[i];
        __nv_bfloat16 h = __float2bfloat16_rn(x);
        __nv_bfloat16 l = __float2bfloat16_rn(x - __bfloat162float(h));
        __nv_bfloat16* p = Bs + n * GM_STR + 3 * kk;
        p[0] = h; p[1] = h; p[2] = l;
    }
}

template <bool RELU, bool BIAS>
__global__ __launch_bounds__(GM_TPB)
void gemm_mma(const float* Ap, int asel,
              const float* __restrict__ W,
              const float* __restrict__ bias,
              float* Cp, int csel,
              int M, int K, int Nc) {
    extern __shared__ __align__(16) char smem_raw[];
    __nv_bfloat16* Abuf = (__nv_bfloat16*)smem_raw;      // [2][GM_TILE]
    __nv_bfloat16* Bbuf = Abuf + 2 * GM_TILE;            // [2][GM_TILE]

    const float* A = rbuf(Ap, asel);
    float*       C = wbuf(Cp, csel);
    const int tid = threadIdx.x;
    const int wid = tid >> 5, lane = tid & 31;
    const int g = lane >> 2, tg = lane & 3;
    const int bm = blockIdx.x * 128, bn = blockIdx.y * 128;
    const int wm = (wid & 1) * 64, wn = (wid >> 1) * 32;

    float acc[4][4][4];
#pragma unroll
    for (int i = 0; i < 4; ++i)
#pragma unroll
        for (int j = 0; j < 4; ++j)
#pragma unroll
            for (int q = 0; q < 4; ++q) acc[i][j][q] = 0.0f;

    const int nch = K >> 4;
    float ra[8], rb[8];

    // prologue: stage chunk 0
    ld_chunkA(A, M, K, bm, 0, tid, ra);
    ld_chunkB(W, Nc, bn, 0, tid, rb);
    st_chunkA(Abuf, tid, ra);
    st_chunkB(Bbuf, tid, rb);
    __syncthreads();

    for (int c = 0; c < nch; ++c) {
        if (c + 1 < nch) {
            ld_chunkA(A, M, K, bm, (c + 1) << 4, tid, ra);
            ld_chunkB(W, Nc, bn, (c + 1) << 4, tid, rb);
        }
        // compute on buffer c&1
        const __nv_bfloat16* Asb = Abuf + (c & 1) * GM_TILE;
        const __nv_bfloat16* Bsb = Bbuf + (c & 1) * GM_TILE;
#pragma unroll
        for (int ks = 0; ks < 3; ++ks) {
            const int kb = ks * 16 + 2 * tg;
            uint32_t af[4][4], bf[4][2];
#pragma unroll
            for (int i = 0; i < 4; ++i) {
                const int r0 = wm + i * 16 + g;
                af[i][0] = *(const uint32_t*)(Asb + r0 * GM_STR + kb);
                af[i][1] = *(const uint32_t*)(Asb + (r0 + 8) * GM_STR + kb);
                af[i][2] = *(const uint32_t*)(Asb + r0 * GM_STR + kb + 8);
                af[i][3] = *(const uint32_t*)(Asb + (r0 + 8) * GM_STR + kb + 8);
            }
#pragma unroll
            for (int j = 0; j < 4; ++j) {
                const int cc = wn + j * 8 + g;
                bf[j][0] = *(const uint32_t*)(Bsb + cc * GM_STR + kb);
                bf[j][1] = *(const uint32_t*)(Bsb + cc * GM_STR + kb + 8);
            }
#pragma unroll
            for (int i = 0; i < 4; ++i)
#pragma unroll
                for (int j = 0; j < 4; ++j)
                    mma16816(acc[i][j], af[i], bf[j]);
        }
        __syncthreads();
        if (c + 1 < nch) {
            st_chunkA(Abuf + ((c + 1) & 1) * GM_TILE, tid, ra);
            st_chunkB(Bbuf + ((c + 1) & 1) * GM_TILE, tid, rb);
            __syncthreads();
        }
    }

    // epilogue
#pragma unroll
    for (int i = 0; i < 4; ++i) {
        const int r0 = bm + wm + i * 16 + g;
#pragma unroll
        for (int j = 0; j < 4; ++j) {
            const int col = bn + wn + j * 8 + 2 * tg;
            float v0 = acc[i][j][0], v1 = acc[i][j][1];
            float v2 = acc[i][j][2], v3 = acc[i][j][3];
            if (BIAS) {
                float bb0 = bias[col], bb1 = bias[col + 1];
                v0 += bb0; v1 += bb1; v2 += bb0; v3 += bb1;
            }
            if (RELU) {
                v0 = fmaxf(v0, 0.0f); v1 = fmaxf(v1, 0.0f);
                v2 = fmaxf(v2, 0.0f); v3 = fmaxf(v3, 0.0f);
            }
            if (r0 < M)
                *(float2*)(C + (size_t)r0 * Nc + col) = make_float2(v0, v1);
            if (r0 + 8 < M)
                *(float2*)(C + (size_t)(r0 + 8) * Nc + col) = make_float2(v2, v3);
        }
    }
}

// ---------------- tiny GEMM for final layer: [NN,256] @ [256,6] ----------
__global__ void gemm6_kernel(const float* __restrict__ W) {
    const float* A = g_bufB;
    float*       C = g_bufA;
    int gt = blockIdx.x * blockDim.x + threadIdx.x;
    int row = gt >> 5;
    int lane = gt & 31;
    if (row >= NN) return;
    float acc[6] = {0.f, 0.f, 0.f, 0.f, 0.f, 0.f};
    const float* a = A + (size_t)row * 256;
    for (int k = lane; k < 256; k += 32) {
        float av = a[k];
        const float* wr = W + k * 6;
#pragma unroll
        for (int j = 0; j < 6; ++j) acc[j] = fmaf(av, wr[j], acc[j]);
    }
#pragma unroll
    for (int j = 0; j < 6; ++j)
#pragma unroll
        for (int off = 16; off > 0; off >>= 1)
            acc[j] += __shfl_xor_sync(0xFFFFFFFFu, acc[j], off);
    if (lane < 6) C[(size_t)row * 6 + lane] = acc[lane];
}

// ---------------- host pipeline ----------------
extern "C" void kernel_launch(void* const* d_in, const int* in_sizes, int n_in,
                              void* d_out, int out_size) {
    const float* x  = (const float*)d_in[0];
    const int*   ei = (const int*)d_in[1];
    const float* W1 = (const float*)d_in[2];
    const float* b1 = (const float*)d_in[3];
    const float* W2 = (const float*)d_in[4];
    const float* b2 = (const float*)d_in[5];
    const float* W3 = (const float*)d_in[6];
    const float* b3 = (const float*)d_in[7];
    const float* W4 = (const float*)d_in[8];
    const float* b4 = (const float*)d_in[9];
    const float* W5 = (const float*)d_in[10];
    const float* b5 = (const float*)d_in[11];
    float* out = (float*)d_out;

    const int E = in_sizes[1] / 2;

    cudaFuncSetAttribute(gemm_mma<true, true>,
                         cudaFuncAttributeMaxDynamicSharedMemorySize, GM_SMEM);
    cudaFuncSetAttribute(gemm_mma<false, false>,
                         cudaFuncAttributeMaxDynamicSharedMemorySize, GM_SMEM);

    const int TPB = 256;
    const int gN = (NN + TPB - 1) / TPB;
    const int gE = (E + TPB - 1) / TPB;
    const int gWarp = ((NN * 32) + TPB - 1) / TPB;
    const int gM = (NN + 127) / 128;   // 782

    // ---- CSR + norm ----
    k_init_deg<<<gN, TPB>>>();
    k_count<<<gE, TPB>>>(ei, E);
    k_scan<<<1, 1024>>>();
    k_node_prep<<<gN, TPB>>>();
    k_fill_edges<<<gE, TPB>>>(ei, E);

    // ---- Layer 1: agg(x) [F=32] -> MMA GEMM 32x256 + b1 + relu ----
    agg_warp_kernel<32, false, false><<<gWarp, TPB>>>(x, -1, nullptr, 0, nullptr);
    gemm_mma<true, true><<<dim3(gM, 2), GM_TPB, GM_SMEM>>>(
        nullptr, 0, W1, b1, nullptr, 1, NN, 32, 256);

    // ---- Layer 2: agg [F=256] -> MMA GEMM 256x1024 + b2 + relu ----
    agg_block_kernel<256, false, false><<<NN, TPB>>>(nullptr, 1, nullptr, 0, nullptr);
    gemm_mma<true, true><<<dim3(gM, 8), GM_TPB, GM_SMEM>>>(
        nullptr, 0, W2, b2, nullptr, 1, NN, 256, 1024);

    // ---- Layer 3: agg [F=1024] -> MMA GEMM 1024x1024 + b3 + relu ----
    agg_block_kernel<1024, false, false><<<NN, TPB>>>(nullptr, 1, nullptr, 0, nullptr);
    gemm_mma<true, true><<<dim3(gM, 8), GM_TPB, GM_SMEM>>>(
        nullptr, 0, W3, b3, nullptr, 1, NN, 1024, 1024);

    // ---- Layer 4: MMA GEMM 1024x256 (no bias/relu) -> agg [F=256] + b4 + relu
    gemm_mma<false, false><<<dim3(gM, 2), GM_TPB, GM_SMEM>>>(
        nullptr, 1, W4, nullptr, nullptr, 0, NN, 1024, 256);
    agg_block_kernel<256, true, true><<<NN, TPB>>>(nullptr, 0, nullptr, 1, b4);

    // ---- Layer 5: GEMM 256x6 -> agg [F=6] + b5 ----
    gemm6_kernel<<<gWarp, TPB>>>(W5);
    agg_warp_kernel<6, false, true><<<gWarp, TPB>>>(nullptr, 0, out, -1, b5);
}

// round 12
// speedup vs baseline: 1.2782x; 1.0623x over previous
#include <cuda_runtime.h>
#include <cuda_bf16.h>
#include <cstdint>
#include <cstddef>

#define NN 100000
#define MAXE 3300000

// ---------------- scratch ----------------
__device__ int   g_deg[NN];
__device__ float g_dinv[NN];
__device__ int   g_rowptr[NN + 1];
__device__ int   g_cursor[NN];
__device__ int   g_col[MAXE];
__device__ __align__(16) float g_bufA[(size_t)NN * 1024];
__device__ __align__(16) float g_bufB[(size_t)NN * 1024];
// expanded bf16 activations (A-slots: hi, lo, hi), max row = 3*1024
__device__ __align__(16) __nv_bfloat16 g_expA[(size_t)NN * 3072];
__device__ __align__(16) __nv_bfloat16 g_expB[(size_t)NN * 3072];
// expanded weights (B-slots: hi, hi, lo), layout [Nc][3K] row-major
#define EXPW1_OFF 0              // 3*32*256    = 24576
#define EXPW2_OFF 24576          // 3*256*1024  = 786432
#define EXPW3_OFF 811008         // 3*1024*1024 = 3145728
#define EXPW4_OFF 3956736        // 3*1024*256  = 786432
#define EXPW_TOT  4743168
__device__ __align__(16) __nv_bfloat16 g_expW[EXPW_TOT];

// ---- ALL global-scratch pointers are resolved ON DEVICE via selectors ----
__device__ __forceinline__ const float* rbuf(const float* p, int sel) {
    if (sel == 0) return g_bufA;
    if (sel == 1) return g_bufB;
    return p;
}
__device__ __forceinline__ float* wbuf(float* p, int sel) {
    if (sel == 0) return g_bufA;
    if (sel == 1) return g_bufB;
    return p;
}
__device__ __forceinline__ const __nv_bfloat16* rexp(int sel) {
    return sel ? g_expB : g_expA;
}
__device__ __forceinline__ __nv_bfloat16* wexp(int sel) {
    return sel ? g_expB : g_expA;
}

__device__ __forceinline__ uint32_t smem_u32(const void* p) {
    uint32_t a;
    asm("{ .reg .u64 t; cvta.to.shared.u64 t, %1; cvt.u32.u64 %0, t; }"
        : "=r"(a) : "l"(p));
    return a;
}

// split x = hi + lo (bf16 each); write A-slot triple (hi, lo, hi)
__device__ __forceinline__ void wexpA(__nv_bfloat16* p, float x) {
    __nv_bfloat16 h = __float2bfloat16_rn(x);
    __nv_bfloat16 l = __float2bfloat16_rn(x - __bfloat162float(h));
    p[0] = h; p[1] = l; p[2] = h;
}

// ---------------- weight expansion: B'[n][3k+s] = (hi,hi,lo) ----------------
__global__ void k_expand_w(const float* __restrict__ W, int K, int Nc, int off) {
    int t = blockIdx.x * blockDim.x + threadIdx.x;
    if (t >= K * Nc) return;
    int n = t / K, k = t - n * K;
    float x = W[(size_t)k * Nc + n];
    __nv_bfloat16 h = __float2bfloat16_rn(x);
    __nv_bfloat16 l = __float2bfloat16_rn(x - __bfloat162float(h));
    __nv_bfloat16* p = g_expW + off + (size_t)n * (3 * K) + 3 * k;
    p[0] = h; p[1] = h; p[2] = l;
}

// ---------------- CSR construction ----------------
__global__ void k_init_deg() {
    int v = blockIdx.x * blockDim.x + threadIdx.x;
    if (v < NN) g_deg[v] = 1;
}
__global__ void k_count(const int* __restrict__ ei, int E) {
    int i = blockIdx.x * blockDim.x + threadIdx.x;
    if (i < E) {
        int d = ei[E + i];
        if ((unsigned)d < NN) atomicAdd(&g_deg[d], 1);
    }
}
__global__ void k_scan() {
    __shared__ int s[1024];
    int tid = threadIdx.x;
    int carry = 0;
    if (tid == 0) g_rowptr[0] = 0;
    for (int base = 0; base < NN; base += 1024) {
        int idx = base + tid;
        int v = (idx < NN) ? g_deg[idx] : 0;
        __syncthreads();
        s[tid] = v;
        __syncthreads();
        for (int off = 1; off < 1024; off <<= 1) {
            int t = (tid >= off) ? s[tid - off] : 0;
            __syncthreads();
            s[tid] += t;
            __syncthreads();
        }
        int incl = s[tid];
        if (idx < NN) {
            g_rowptr[idx + 1] = carry + incl;
            g_cursor[idx]     = carry + incl - v;
        }
        carry += s[1023];
        __syncthreads();
    }
}
__global__ void k_node_prep() {
    int v = blockIdx.x * blockDim.x + threadIdx.x;
    if (v < NN) {
        g_dinv[v] = rsqrtf((float)g_deg[v]);
        int pos = atomicAdd(&g_cursor[v], 1);
        if ((unsigned)pos < MAXE) g_col[pos] = v;
    }
}
__global__ void k_fill_edges(const int* __restrict__ ei, int E) {
    int i = blockIdx.x * blockDim.x + threadIdx.x;
    if (i < E) {
        int srcv = ei[i];
        int dstv = ei[E + i];
        if ((unsigned)srcv < NN && (unsigned)dstv < NN) {
            int pos = atomicAdd(&g_cursor[dstv], 1);
            if ((unsigned)pos < MAXE) g_col[pos] = srcv;
        }
    }
}

// ---------------- aggregation ----------------
// warp-per-node, F <= 32
template <int F, bool EXPAND, bool RELU, bool BIAS>
__global__ void agg_warp_kernel(const float* inp, int insel,
                                float* outp, int outsel,
                                const float* __restrict__ bias) {
    const float* in = rbuf(inp, insel);
    int gt = blockIdx.x * blockDim.x + threadIdx.x;
    int v = gt >> 5;
    int lane = gt & 31;
    if (v >= NN || lane >= F) return;
    float acc = 0.0f;
    int s = g_rowptr[v], e = g_rowptr[v + 1];
    for (int p = s; p < e; ++p) {
        int u = g_col[p];
        acc = fmaf(g_dinv[u], in[(size_t)u * F + lane], acc);
    }
    float val = acc * g_dinv[v];
    if (BIAS) val += bias[lane];
    if (RELU) val = fmaxf(val, 0.0f);
    if (EXPAND) {
        wexpA(g_expA + (size_t)v * (3 * F) + 3 * lane, val);
    } else {
        wbuf(outp, outsel)[(size_t)v * F + lane] = val;
    }
}

// block-per-node slice: 128 cols starting at coloff (L2-blocked gather)
template <bool EXPAND, bool RELU, bool BIAS>
__global__ void agg_slice_kernel(const float* inp, int insel, int Ftot,
                                 float* outp, int outsel,
                                 const float* __restrict__ bias, int coloff) {
    const float* in = rbuf(inp, insel);
    int v = blockIdx.x;
    int tid = threadIdx.x;           // blockDim = 128
    int col = coloff + tid;
    float acc = 0.0f;
    int s = g_rowptr[v], e = g_rowptr[v + 1];
    const float* base = in + col;
    for (int p = s; p < e; ++p) {
        int u = g_col[p];
        acc = fmaf(g_dinv[u], base[(size_t)u * Ftot], acc);
    }
    float val = acc * g_dinv[v];
    if (BIAS) val += bias[col];
    if (RELU) val = fmaxf(val, 0.0f);
    if (EXPAND) {
        wexpA(g_expA + (size_t)v * (3 * Ftot) + 3 * col, val);
    } else {
        wbuf(outp, outsel)[(size_t)v * Ftot + col] = val;
    }
}

// ================= bf16 mma.sync GEMM on pre-expanded operands =============
// C[M,Nc] = A'[M,K3] @ B'[Nc,K3]^T  (K3 = 3K, slot-expanded split precision)
// CTA tile 128m x 128n; 8 warps 64x32; chunk 48 k' (3 ksteps), cp.async
// double buffered. Smem rows padded to 56 bf16 (112B): conflict-free frags.

#define GK_CH   48
#define GK_STR  56
#define GK_TILE (128 * GK_STR)          // 7168 bf16
#define GK_SMEM (4 * GK_TILE * 2)       // 57344 bytes (A0,A1,B0,B1)

__device__ __forceinline__ void mma16816(float* c, const uint32_t* a, const uint32_t* b) {
    asm volatile(
        "mma.sync.aligned.m16n8k16.row.col.f32.bf16.bf16.f32 "
        "{%0,%1,%2,%3}, {%4,%5,%6,%7}, {%8,%9}, {%0,%1,%2,%3};"
        : "+f"(c[0]), "+f"(c[1]), "+f"(c[2]), "+f"(c[3])
        : "r"(a[0]), "r"(a[1]), "r"(a[2]), "r"(a[3]), "r"(b[0]), "r"(b[1]));
}

__device__ __forceinline__ void gk_stage(const __nv_bfloat16* __restrict__ Aexp,
                                         const __nv_bfloat16* __restrict__ Bexp,
                                         __nv_bfloat16* Ab, __nv_bfloat16* Bb,
                                         int c, int bm, int bn, int M, int K3, int tid) {
    const int buf = c & 1;
    const int k0 = c * GK_CH;
#pragma unroll
    for (int i = 0; i < 6; ++i) {
        int cid = tid + i * 256;                 // 0..1535
        int isB = cid >= 768;
        int local = isB ? cid - 768 : cid;
        int row = local / 6;
        int seg = local - row * 6;
        const __nv_bfloat16* src;
        uint32_t dst;
        int nb = 16;
        if (isB) {
            src = Bexp + (size_t)(bn + row) * K3 + k0 + seg * 8;
            dst = smem_u32(Bb + buf * GK_TILE + row * GK_STR + seg * 8);
        } else {
            int gm = bm + row;
            if (gm >= M) gm = 0;                 // keep src in-bounds
            src = Aexp + (size_t)gm * K3 + k0 + seg * 8;
            dst = smem_u32(Ab + buf * GK_TILE + row * GK_STR + seg * 8);
            if (bm + row >= M) nb = 0;           // zero-fill OOB rows
        }
        asm volatile("cp.async.cg.shared.global [%0], [%1], 16, %2;"
                     :: "r"(dst), "l"(src), "r"(nb));
    }
    asm volatile("cp.async.commit_group;");
}

// write expanded pair (next layer's A-slots) for two adjacent columns
__device__ __forceinline__ void wexpA2(__nv_bfloat16* p, float a, float b) {
    __nv_bfloat16 h0 = __float2bfloat16_rn(a);
    __nv_bfloat16 l0 = __float2bfloat16_rn(a - __bfloat162float(h0));
    __nv_bfloat16 h1 = __float2bfloat16_rn(b);
    __nv_bfloat16 l1 = __float2bfloat16_rn(b - __bfloat162float(h1));
    p[0] = h0; p[1] = l0; p[2] = h0;
    p[3] = h1; p[4] = l1; p[5] = h1;
}

// aexp_sel: 0 -> g_expA, 1 -> g_expB ; woff: offset into g_expW
// eout_sel: expanded output target (only if EXPOUT)
template <bool RELU, bool BIAS, bool EXPOUT>
__global__ __launch_bounds__(256)
void gemm_bf16(int aexp_sel, int woff,
               const float* __restrict__ bias,
               float* Cp, int csel, int eout_sel,
               int M, int K3, int Nc) {
    extern __shared__ __align__(16) char smem_raw[];
    __nv_bfloat16* Ab = (__nv_bfloat16*)smem_raw;    // [2][GK_TILE]
    __nv_bfloat16* Bb = Ab + 2 * GK_TILE;            // [2][GK_TILE]
    const __nv_bfloat16* Aexp = rexp(aexp_sel);
    const __nv_bfloat16* Bexp = g_expW + woff;
    __nv_bfloat16* EOut = wexp(eout_sel);
    float* C = wbuf(Cp, csel);
    const int tid = threadIdx.x;
    const int wid = tid >> 5, lane = tid & 31;
    const int g = lane >> 2, tg = lane & 3;
    const int bn = blockIdx.x * 128;   // N in x: consecutive CTAs reuse A in L2
    const int bm = blockIdx.y * 128;
    const int wm = (wid & 1) * 64, wn = (wid >> 1) * 32;

    float acc[4][4][4];
#pragma unroll
    for (int i = 0; i < 4; ++i)
#pragma unroll
        for (int j = 0; j < 4; ++j)
#pragma unroll
            for (int q = 0; q < 4; ++q) acc[i][j][q] = 0.0f;

    const int nch = K3 / GK_CH;
    gk_stage(Aexp, Bexp, Ab, Bb, 0, bm, bn, M, K3, tid);

    for (int c = 0; c < nch; ++c) {
        if (c + 1 < nch) {
            gk_stage(Aexp, Bexp, Ab, Bb, c + 1, bm, bn, M, K3, tid);
            asm volatile("cp.async.wait_group 1;");
        } else {
            asm volatile("cp.async.wait_group 0;");
        }
        __syncthreads();
        const __nv_bfloat16* Asb = Ab + (c & 1) * GK_TILE;
        const __nv_bfloat16* Bsb = Bb + (c & 1) * GK_TILE;
#pragma unroll
        for (int ks = 0; ks < 3; ++ks) {
            const int kb = ks * 16 + 2 * tg;
            uint32_t af[4][4], bf[4][2];
#pragma unroll
            for (int i = 0; i < 4; ++i) {
                const int r0 = wm + i * 16 + g;
                af[i][0] = *(const uint32_t*)(Asb + r0 * GK_STR + kb);
                af[i][1] = *(const uint32_t*)(Asb + (r0 + 8) * GK_STR + kb);
                af[i][2] = *(const uint32_t*)(Asb + r0 * GK_STR + kb + 8);
                af[i][3] = *(const uint32_t*)(Asb + (r0 + 8) * GK_STR + kb + 8);
            }
#pragma unroll
            for (int j = 0; j < 4; ++j) {
                const int cc = wn + j * 8 + g;
                bf[j][0] = *(const uint32_t*)(Bsb + cc * GK_STR + kb);
                bf[j][1] = *(const uint32_t*)(Bsb + cc * GK_STR + kb + 8);
            }
#pragma unroll
            for (int i = 0; i < 4; ++i)
#pragma unroll
                for (int j = 0; j < 4; ++j)
                    mma16816(acc[i][j], af[i], bf[j]);
        }
        __syncthreads();
    }

    // epilogue
#pragma unroll
    for (int i = 0; i < 4; ++i) {
        const int r0 = bm + wm + i * 16 + g;
#pragma unroll
        for (int j = 0; j < 4; ++j) {
            const int col = bn + wn + j * 8 + 2 * tg;
            float v0 = acc[i][j][0], v1 = acc[i][j][1];
            float v2 = acc[i][j][2], v3 = acc[i][j][3];
            if (BIAS) {
                float bb0 = bias[col], bb1 = bias[col + 1];
                v0 += bb0; v1 += bb1; v2 += bb0; v3 += bb1;
            }
            if (RELU) {
                v0 = fmaxf(v0, 0.0f); v1 = fmaxf(v1, 0.0f);
                v2 = fmaxf(v2, 0.0f); v3 = fmaxf(v3, 0.0f);
            }
            if (EXPOUT) {
                if (r0 < M)
                    wexpA2(EOut + (size_t)r0 * (3 * Nc) + 3 * col, v0, v1);
                if (r0 + 8 < M)
                    wexpA2(EOut + (size_t)(r0 + 8) * (3 * Nc) + 3 * col, v2, v3);
            } else {
                if (r0 < M)
                    *(float2*)(C + (size_t)r0 * Nc + col) = make_float2(v0, v1);
                if (r0 + 8 < M)
                    *(float2*)(C + (size_t)(r0 + 8) * Nc + col) = make_float2(v2, v3);
            }
        }
    }
}

// ---------------- tiny GEMM for final layer: [NN,256] @ [256,6] ----------
__global__ void gemm6_kernel(const float* __restrict__ W) {
    const float* A = g_bufB;
    float*       C = g_bufA;
    int gt = blockIdx.x * blockDim.x + threadIdx.x;
    int row = gt >> 5;
    int lane = gt & 31;
    if (row >= NN) return;
    float acc[6] = {0.f, 0.f, 0.f, 0.f, 0.f, 0.f};
    const float* a = A + (size_t)row * 256;
    for (int k = lane; k < 256; k += 32) {
        float av = a[k];
        const float* wr = W + k * 6;
#pragma unroll
        for (int j = 0; j < 6; ++j) acc[j] = fmaf(av, wr[j], acc[j]);
    }
#pragma unroll
    for (int j = 0; j < 6; ++j)
#pragma unroll
        for (int off = 16; off > 0; off >>= 1)
            acc[j] += __shfl_xor_sync(0xFFFFFFFFu, acc[j], off);
    if (lane < 6) C[(size_t)row * 6 + lane] = acc[lane];
}

// ---------------- host pipeline ----------------
extern "C" void kernel_launch(void* const* d_in, const int* in_sizes, int n_in,
                              void* d_out, int out_size) {
    const float* x  = (const float*)d_in[0];
    const int*   ei = (const int*)d_in[1];
    const float* W1 = (const float*)d_in[2];
    const float* b1 = (const float*)d_in[3];
    const float* W2 = (const float*)d_in[4];
    const float* b2 = (const float*)d_in[5];
    const float* W3 = (const float*)d_in[6];
    const float* b3 = (const float*)d_in[7];
    const float* W4 = (const float*)d_in[8];
    const float* b4 = (const float*)d_in[9];
    const float* W5 = (const float*)d_in[10];
    const float* b5 = (const float*)d_in[11];
    float* out = (float*)d_out;

    const int E = in_sizes[1] / 2;

    cudaFuncSetAttribute(gemm_bf16<true, true, false>,
                         cudaFuncAttributeMaxDynamicSharedMemorySize, GK_SMEM);
    cudaFuncSetAttribute(gemm_bf16<true, true, true>,
                         cudaFuncAttributeMaxDynamicSharedMemorySize, GK_SMEM);
    cudaFuncSetAttribute(gemm_bf16<false, false, false>,
                         cudaFuncAttributeMaxDynamicSharedMemorySize, GK_SMEM);

    const int TPB = 256;
    const int gN = (NN + TPB - 1) / TPB;
    const int gE = (E + TPB - 1) / TPB;
    const int gWarp = ((NN * 32) + TPB - 1) / TPB;
    const int gM = (NN + 127) / 128;   // 782

    // ---- CSR + norm ----
    k_init_deg<<<gN, TPB>>>();
    k_count<<<gE, TPB>>>(ei, E);
    k_scan<<<1, 1024>>>();
    k_node_prep<<<gN, TPB>>>();
    k_fill_edges<<<gE, TPB>>>(ei, E);

    // ---- expand weights (once per launch; B-slots) ----
    k_expand_w<<<(32 * 256 + 255) / 256, 256>>>(W1, 32, 256, EXPW1_OFF);
    k_expand_w<<<(256 * 1024 + 255) / 256, 256>>>(W2, 256, 1024, EXPW2_OFF);
    k_expand_w<<<(1024 * 1024 + 255) / 256, 256>>>(W3, 1024, 1024, EXPW3_OFF);
    k_expand_w<<<(1024 * 256 + 255) / 256, 256>>>(W4, 1024, 256, EXPW4_OFF);

    // ---- Layer 1: agg(x) [F=32] -> expand(g_expA) -> GEMM1 -> bufB ----
    agg_warp_kernel<32, true, false, false><<<gWarp, TPB>>>(x, -1, nullptr, -1, nullptr);
    gemm_bf16<true, true, false><<<dim3(2, gM), 256, GK_SMEM>>>(
        0, EXPW1_OFF, b1, nullptr, 1, 0, NN, 96, 256);

    // ---- Layer 2: agg slices (bufB) -> expand(g_expA) -> GEMM2 -> bufA ----
    for (int sl = 0; sl < 2; ++sl)
        agg_slice_kernel<true, false, false><<<NN, 128>>>(nullptr, 1, 256,
                                                          nullptr, -1, nullptr, sl * 128);
    gemm_bf16<true, true, false><<<dim3(8, gM), 256, GK_SMEM>>>(
        0, EXPW2_OFF, b2, nullptr, 0, 0, NN, 768, 1024);

    // ---- Layer 3: agg slices (bufA) -> expand(g_expA) -> GEMM3 -> g_expB ----
    for (int sl = 0; sl < 8; ++sl)
        agg_slice_kernel<true, false, false><<<NN, 128>>>(nullptr, 0, 1024,
                                                          nullptr, -1, nullptr, sl * 128);
    gemm_bf16<true, true, true><<<dim3(8, gM), 256, GK_SMEM>>>(
        0, EXPW3_OFF, b3, nullptr, -1, 1, NN, 3072, 1024);

    // ---- Layer 4: GEMM4 (g_expB) -> bufA ; agg slices + b4 + relu -> bufB --
    gemm_bf16<false, false, false><<<dim3(2, gM), 256, GK_SMEM>>>(
        1, EXPW4_OFF, nullptr, nullptr, 0, 0, NN, 3072, 256);
    for (int sl = 0; sl < 2; ++sl)
        agg_slice_kernel<false, true, true><<<NN, 128>>>(nullptr, 0, 256,
                                                         nullptr, 1, b4, sl * 128);

    // ---- Layer 5: GEMM 256x6 (bufB -> bufA) -> agg [F=6] + b5 -> out ----
    gemm6_kernel<<<gWarp, TPB>>>(W5);
    agg_warp_kernel<6, false, false, true><<<gWarp, TPB>>>(nullptr, 0, out, -1, b5);
}

// round 13
// speedup vs baseline: 1.5023x; 1.1753x over previous
#include <cuda_runtime.h>
#include <cuda_bf16.h>
#include <cstdint>
#include <cstddef>

#define NN 100000
#define MAXE 3300000

// ---------------- scratch ----------------
__device__ int   g_deg[NN];
__device__ float g_dinv[NN];
__device__ int   g_rowptr[NN + 1];
__device__ int   g_cursor[NN];
__device__ int   g_col[MAXE];
__device__ __align__(16) float g_bufA[(size_t)NN * 1024];
__device__ __align__(16) float g_bufB[(size_t)NN * 1024];
__device__ __align__(16) __nv_bfloat16 g_expA[(size_t)NN * 3072];
__device__ __align__(16) __nv_bfloat16 g_expB[(size_t)NN * 3072];
// expanded weights (B-slots: hi, hi, lo), layout [Nc][3K] row-major
#define EXPW1_OFF 0              // 3*32*256    = 24576
#define EXPW2_OFF 24576          // 3*256*1024  = 786432
#define EXPW3_OFF 811008         // 3*1024*1024 = 3145728
#define EXPW4_OFF 3956736        // 3*1024*256  = 786432
#define EXPW_TOT  4743168
__device__ __align__(16) __nv_bfloat16 g_expW[EXPW_TOT];

// ---- ALL global-scratch pointers resolved ON DEVICE via selectors ----
__device__ __forceinline__ const float* rbuf(const float* p, int sel) {
    if (sel == 0) return g_bufA;
    if (sel == 1) return g_bufB;
    return p;
}
__device__ __forceinline__ float* wbuf(float* p, int sel) {
    if (sel == 0) return g_bufA;
    if (sel == 1) return g_bufB;
    return p;
}
__device__ __forceinline__ const __nv_bfloat16* rexp(int sel) {
    return sel ? g_expB : g_expA;
}
__device__ __forceinline__ __nv_bfloat16* wexp(int sel) {
    return sel ? g_expB : g_expA;
}

__device__ __forceinline__ uint32_t smem_u32(const void* p) {
    uint32_t a;
    asm("{ .reg .u64 t; cvta.to.shared.u64 t, %1; cvt.u32.u64 %0, t; }"
        : "=r"(a) : "l"(p));
    return a;
}

__device__ __forceinline__ void wexpA(__nv_bfloat16* p, float x) {
    __nv_bfloat16 h = __float2bfloat16_rn(x);
    __nv_bfloat16 l = __float2bfloat16_rn(x - __bfloat162float(h));
    p[0] = h; p[1] = l; p[2] = h;
}

// ---------------- weight expansion: B'[n][3k+s] = (hi,hi,lo) ---------------
__global__ void k_expand_w(const float* __restrict__ W, int K, int Nc, int off) {
    int t = blockIdx.x * blockDim.x + threadIdx.x;
    if (t >= K * Nc) return;
    int n = t / K, k = t - n * K;
    float x = W[(size_t)k * Nc + n];
    __nv_bfloat16 h = __float2bfloat16_rn(x);
    __nv_bfloat16 l = __float2bfloat16_rn(x - __bfloat162float(h));
    __nv_bfloat16* p = g_expW + off + (size_t)n * (3 * K) + 3 * k;
    p[0] = h; p[1] = h; p[2] = l;
}

// ---------------- CSR construction ----------------
__global__ void k_init_deg() {
    int v = blockIdx.x * blockDim.x + threadIdx.x;
    if (v < NN) g_deg[v] = 1;
}
__global__ void k_count(const int* __restrict__ ei, int E) {
    int i = blockIdx.x * blockDim.x + threadIdx.x;
    if (i < E) {
        int d = ei[E + i];
        if ((unsigned)d < NN) atomicAdd(&g_deg[d], 1);
    }
}
__global__ void k_scan() {
    __shared__ int s[1024];
    int tid = threadIdx.x;
    int carry = 0;
    if (tid == 0) g_rowptr[0] = 0;
    for (int base = 0; base < NN; base += 1024) {
        int idx = base + tid;
        int v = (idx < NN) ? g_deg[idx] : 0;
        __syncthreads();
        s[tid] = v;
        __syncthreads();
        for (int off = 1; off < 1024; off <<= 1) {
            int t = (tid >= off) ? s[tid - off] : 0;
            __syncthreads();
            s[tid] += t;
            __syncthreads();
        }
        int incl = s[tid];
        if (idx < NN) {
            g_rowptr[idx + 1] = carry + incl;
            g_cursor[idx]     = carry + incl - v;
        }
        carry += s[1023];
        __syncthreads();
    }
}
__global__ void k_node_prep() {
    int v = blockIdx.x * blockDim.x + threadIdx.x;
    if (v < NN) {
        g_dinv[v] = rsqrtf((float)g_deg[v]);
        int pos = atomicAdd(&g_cursor[v], 1);
        if ((unsigned)pos < MAXE) g_col[pos] = v;
    }
}
__global__ void k_fill_edges(const int* __restrict__ ei, int E) {
    int i = blockIdx.x * blockDim.x + threadIdx.x;
    if (i < E) {
        int srcv = ei[i];
        int dstv = ei[E + i];
        if ((unsigned)srcv < NN && (unsigned)dstv < NN) {
            int pos = atomicAdd(&g_cursor[dstv], 1);
            if ((unsigned)pos < MAXE) g_col[pos] = srcv;
        }
    }
}

// ---------------- aggregation ----------------
template <int F, bool EXPAND, bool RELU, bool BIAS>
__global__ void agg_warp_kernel(const float* inp, int insel,
                                float* outp, int outsel,
                                const float* __restrict__ bias) {
    const float* in = rbuf(inp, insel);
    int gt = blockIdx.x * blockDim.x + threadIdx.x;
    int v = gt >> 5;
    int lane = gt & 31;
    if (v >= NN || lane >= F) return;
    float acc = 0.0f;
    int s = g_rowptr[v], e = g_rowptr[v + 1];
    for (int p = s; p < e; ++p) {
        int u = g_col[p];
        acc = fmaf(g_dinv[u], in[(size_t)u * F + lane], acc);
    }
    float val = acc * g_dinv[v];
    if (BIAS) val += bias[lane];
    if (RELU) val = fmaxf(val, 0.0f);
    if (EXPAND) {
        wexpA(g_expA + (size_t)v * (3 * F) + 3 * lane, val);
    } else {
        wbuf(outp, outsel)[(size_t)v * F + lane] = val;
    }
}

template <bool EXPAND, bool RELU, bool BIAS>
__global__ void agg_slice_kernel(const float* inp, int insel, int Ftot,
                                 float* outp, int outsel,
                                 const float* __restrict__ bias, int coloff) {
    const float* in = rbuf(inp, insel);
    int v = blockIdx.x;
    int tid = threadIdx.x;           // blockDim = 128
    int col = coloff + tid;
    float acc = 0.0f;
    int s = g_rowptr[v], e = g_rowptr[v + 1];
    const float* base = in + col;
    for (int p = s; p < e; ++p) {
        int u = g_col[p];
        acc = fmaf(g_dinv[u], base[(size_t)u * Ftot], acc);
    }
    float val = acc * g_dinv[v];
    if (BIAS) val += bias[col];
    if (RELU) val = fmaxf(val, 0.0f);
    if (EXPAND) {
        wexpA(g_expA + (size_t)v * (3 * Ftot) + 3 * col, val);
    } else {
        wbuf(outp, outsel)[(size_t)v * Ftot + col] = val;
    }
}

// ================= bf16 mma.sync GEMM, ldmatrix + 3-stage cp.async =========
// C[M,Nc] = A'[M,K3] @ B'[Nc,K3]^T  (K3 = 3K, slot-expanded split precision)
// CTA tile 128m x 128n; 8 warps each 64x32; chunk 48 k'; 3-stage pipeline,
// one __syncthreads per chunk. Rows padded to 56 bf16 (112B): the 8 rows of
// every ldmatrix start at banks 28r mod 32 (distinct) -> conflict-free LDSM.

#define GK_CH    48
#define GK_STR   56
#define GK_HALF  (128 * GK_STR * 2)       // 14336 B per operand per stage
#define GK_STAGE (2 * GK_HALF)            // 28672 B
#define GK_NST   3
#define GK_SMEM  (GK_NST * GK_STAGE)      // 86016 B

__device__ __forceinline__ void mma16816(float* c, const uint32_t* a, const uint32_t* b) {
    asm volatile(
        "mma.sync.aligned.m16n8k16.row.col.f32.bf16.bf16.f32 "
        "{%0,%1,%2,%3}, {%4,%5,%6,%7}, {%8,%9}, {%0,%1,%2,%3};"
        : "+f"(c[0]), "+f"(c[1]), "+f"(c[2]), "+f"(c[3])
        : "r"(a[0]), "r"(a[1]), "r"(a[2]), "r"(a[3]), "r"(b[0]), "r"(b[1]));
}

__device__ __forceinline__ void ldsm_x4(uint32_t* r, uint32_t addr) {
    asm volatile("ldmatrix.sync.aligned.m8n8.x4.shared.b16 {%0,%1,%2,%3}, [%4];"
        : "=r"(r[0]), "=r"(r[1]), "=r"(r[2]), "=r"(r[3]) : "r"(addr));
}

__device__ __forceinline__ void gk_stage(const __nv_bfloat16* __restrict__ Aexp,
                                         const __nv_bfloat16* __restrict__ Bexp,
                                         char* smem_base, int c,
                                         int bm, int bn, int M, int K3, int tid) {
    char* st = smem_base + (c % GK_NST) * GK_STAGE;
    __nv_bfloat16* Ab = (__nv_bfloat16*)st;
    __nv_bfloat16* Bb = (__nv_bfloat16*)(st + GK_HALF);
    const int k0 = c * GK_CH;
#pragma unroll
    for (int i = 0; i < 6; ++i) {
        int cid = tid + i * 256;                 // 0..1535
        int isB = cid >= 768;
        int local = isB ? cid - 768 : cid;
        int row = local / 6;
        int seg = local - row * 6;
        const __nv_bfloat16* src;
        uint32_t dst;
        int nb = 16;
        if (isB) {
            src = Bexp + (size_t)(bn + row) * K3 + k0 + seg * 8;
            dst = smem_u32(Bb + row * GK_STR + seg * 8);
        } else {
            int gm = bm + row;
            if (gm >= M) gm = 0;                 // keep src in-bounds
            src = Aexp + (size_t)gm * K3 + k0 + seg * 8;
            dst = smem_u32(Ab + row * GK_STR + seg * 8);
            if (bm + row >= M) nb = 0;           // zero-fill OOB rows
        }
        asm volatile("cp.async.cg.shared.global [%0], [%1], 16, %2;"
                     :: "r"(dst), "l"(src), "r"(nb));
    }
    asm volatile("cp.async.commit_group;");
}

__device__ __forceinline__ void wexpA2(__nv_bfloat16* p, float a, float b) {
    __nv_bfloat16 h0 = __float2bfloat16_rn(a);
    __nv_bfloat16 l0 = __float2bfloat16_rn(a - __bfloat162float(h0));
    __nv_bfloat16 h1 = __float2bfloat16_rn(b);
    __nv_bfloat16 l1 = __float2bfloat16_rn(b - __bfloat162float(h1));
    p[0] = h0; p[1] = l0; p[2] = h0;
    p[3] = h1; p[4] = l1; p[5] = h1;
}

// aexp_sel: 0->g_expA, 1->g_expB ; woff: offset into g_expW
template <bool RELU, bool BIAS, bool EXPOUT>
__global__ __launch_bounds__(256, 2)
void gemm_bf16(int aexp_sel, int woff,
               const float* __restrict__ bias,
               float* Cp, int csel, int eout_sel,
               int M, int K3, int Nc) {
    extern __shared__ __align__(16) char smem_raw[];
    const __nv_bfloat16* Aexp = rexp(aexp_sel);
    const __nv_bfloat16* Bexp = g_expW + woff;
    __nv_bfloat16* EOut = wexp(eout_sel);
    float* C = wbuf(Cp, csel);
    const int tid = threadIdx.x;
    const int wid = tid >> 5, lane = tid & 31;
    const int g = lane >> 2, tg = lane & 3;
    const int bn = blockIdx.x * 128;   // N fastest: consecutive CTAs share A in L2
    const int bm = blockIdx.y * 128;
    const int wm = (wid & 1) * 64, wn = (wid >> 1) * 32;

    // ldmatrix lane-offsets (element units)
    const int a_mlane = ((lane >> 3) & 1) * 8 + (lane & 7);   // m within 16
    const int a_klane = ((lane >> 4) & 1) * 8;                // k half
    const int b_nlane = ((lane >> 4) & 1) * 8 + (lane & 7);   // n within 16
    const int b_klane = ((lane >> 3) & 1) * 8;                // k half

    float acc[4][4][4];
#pragma unroll
    for (int i = 0; i < 4; ++i)
#pragma unroll
        for (int j = 0; j < 4; ++j)
#pragma unroll
            for (int q = 0; q < 4; ++q) acc[i][j][q] = 0.0f;

    const int nch = K3 / GK_CH;
    gk_stage(Aexp, Bexp, smem_raw, 0, bm, bn, M, K3, tid);
    if (nch > 1) gk_stage(Aexp, Bexp, smem_raw, 1, bm, bn, M, K3, tid);

    for (int c = 0; c < nch; ++c) {
        if (c == nch - 1) asm volatile("cp.async.wait_group 0;");
        else              asm volatile("cp.async.wait_group 1;");
        __syncthreads();
        if (c + 2 < nch)
            gk_stage(Aexp, Bexp, smem_raw, c + 2, bm, bn, M, K3, tid);

        char* st = smem_raw + (c % GK_NST) * GK_STAGE;
        const uint32_t sA = smem_u32(st);
        const uint32_t sB = sA + GK_HALF;
        // per-warp ldmatrix base addresses (bytes)
        const uint32_t aBase = sA + 2u * ((wm + a_mlane) * GK_STR + a_klane);
        const uint32_t bBase = sB + 2u * ((wn + b_nlane) * GK_STR + b_klane);
#pragma unroll
        for (int ks = 0; ks < 3; ++ks) {
            const int kb2 = ks * 32;             // ks*16 elems * 2 bytes
            uint32_t af[4][4], bf[4][2];
#pragma unroll
            for (int i = 0; i < 4; ++i)
                ldsm_x4(af[i], aBase + (uint32_t)(i * 16 * GK_STR * 2) + kb2);
#pragma unroll
            for (int p = 0; p < 2; ++p) {
                uint32_t r[4];
                ldsm_x4(r, bBase + (uint32_t)(p * 16 * GK_STR * 2) + kb2);
                bf[2 * p][0] = r[0]; bf[2 * p][1] = r[1];
                bf[2 * p + 1][0] = r[2]; bf[2 * p + 1][1] = r[3];
            }
#pragma unroll
            for (int i = 0; i < 4; ++i)
#pragma unroll
                for (int j = 0; j < 4; ++j)
                    mma16816(acc[i][j], af[i], bf[j]);
        }
        __syncthreads();
    }

    // epilogue
#pragma unroll
    for (int i = 0; i < 4; ++i) {
        const int r0 = bm + wm + i * 16 + g;
#pragma unroll
        for (int j = 0; j < 4; ++j) {
            const int col = bn + wn + j * 8 + 2 * tg;
            float v0 = acc[i][j][0], v1 = acc[i][j][1];
            float v2 = acc[i][j][2], v3 = acc[i][j][3];
            if (BIAS) {
                float bb0 = bias[col], bb1 = bias[col + 1];
                v0 += bb0; v1 += bb1; v2 += bb0; v3 += bb1;
            }
            if (RELU) {
                v0 = fmaxf(v0, 0.0f); v1 = fmaxf(v1, 0.0f);
                v2 = fmaxf(v2, 0.0f); v3 = fmaxf(v3, 0.0f);
            }
            if (EXPOUT) {
                if (r0 < M)
                    wexpA2(EOut + (size_t)r0 * (3 * Nc) + 3 * col, v0, v1);
                if (r0 + 8 < M)
                    wexpA2(EOut + (size_t)(r0 + 8) * (3 * Nc) + 3 * col, v2, v3);
            } else {
                if (r0 < M)
                    *(float2*)(C + (size_t)r0 * Nc + col) = make_float2(v0, v1);
                if (r0 + 8 < M)
                    *(float2*)(C + (size_t)(r0 + 8) * Nc + col) = make_float2(v2, v3);
            }
        }
    }
}

// ---------------- tiny GEMM for final layer: [NN,256] @ [256,6] ----------
__global__ void gemm6_kernel(const float* __restrict__ W) {
    const float* A = g_bufB;
    float*       C = g_bufA;
    int gt = blockIdx.x * blockDim.x + threadIdx.x;
    int row = gt >> 5;
    int lane = gt & 31;
    if (row >= NN) return;
    float acc[6] = {0.f, 0.f, 0.f, 0.f, 0.f, 0.f};
    const float* a = A + (size_t)row * 256;
    for (int k = lane; k < 256; k += 32) {
        float av = a[k];
        const float* wr = W + k * 6;
#pragma unroll
        for (int j = 0; j < 6; ++j) acc[j] = fmaf(av, wr[j], acc[j]);
    }
#pragma unroll
    for (int j = 0; j < 6; ++j)
#pragma unroll
        for (int off = 16; off > 0; off >>= 1)
            acc[j] += __shfl_xor_sync(0xFFFFFFFFu, acc[j], off);
    if (lane < 6) C[(size_t)row * 6 + lane] = acc[lane];
}

// ---------------- host pipeline ----------------
extern "C" void kernel_launch(void* const* d_in, const int* in_sizes, int n_in,
                              void* d_out, int out_size) {
    const float* x  = (const float*)d_in[0];
    const int*   ei = (const int*)d_in[1];
    const float* W1 = (const float*)d_in[2];
    const float* b1 = (const float*)d_in[3];
    const float* W2 = (const float*)d_in[4];
    const float* b2 = (const float*)d_in[5];
    const float* W3 = (const float*)d_in[6];
    const float* b3 = (const float*)d_in[7];
    const float* W4 = (const float*)d_in[8];
    const float* b4 = (const float*)d_in[9];
    const float* W5 = (const float*)d_in[10];
    const float* b5 = (const float*)d_in[11];
    float* out = (float*)d_out;

    const int E = in_sizes[1] / 2;

    cudaFuncSetAttribute(gemm_bf16<true, true, false>,
                         cudaFuncAttributeMaxDynamicSharedMemorySize, GK_SMEM);
    cudaFuncSetAttribute(gemm_bf16<true, true, true>,
                         cudaFuncAttributeMaxDynamicSharedMemorySize, GK_SMEM);
    cudaFuncSetAttribute(gemm_bf16<false, false, false>,
                         cudaFuncAttributeMaxDynamicSharedMemorySize, GK_SMEM);

    const int TPB = 256;
    const int gN = (NN + TPB - 1) / TPB;
    const int gE = (E + TPB - 1) / TPB;
    const int gWarp = ((NN * 32) + TPB - 1) / TPB;
    const int gM = (NN + 127) / 128;   // 782

    // ---- CSR + norm ----
    k_init_deg<<<gN, TPB>>>();
    k_count<<<gE, TPB>>>(ei, E);
    k_scan<<<1, 1024>>>();
    k_node_prep<<<gN, TPB>>>();
    k_fill_edges<<<gE, TPB>>>(ei, E);

    // ---- expand weights (B-slots) ----
    k_expand_w<<<(32 * 256 + 255) / 256, 256>>>(W1, 32, 256, EXPW1_OFF);
    k_expand_w<<<(256 * 1024 + 255) / 256, 256>>>(W2, 256, 1024, EXPW2_OFF);
    k_expand_w<<<(1024 * 1024 + 255) / 256, 256>>>(W3, 1024, 1024, EXPW3_OFF);
    k_expand_w<<<(1024 * 256 + 255) / 256, 256>>>(W4, 1024, 256, EXPW4_OFF);

    // ---- Layer 1: agg(x) [F=32] -> expand(g_expA) -> GEMM1 -> bufB ----
    agg_warp_kernel<32, true, false, false><<<gWarp, TPB>>>(x, -1, nullptr, -1, nullptr);
    gemm_bf16<true, true, false><<<dim3(2, gM), 256, GK_SMEM>>>(
        0, EXPW1_OFF, b1, nullptr, 1, 0, NN, 96, 256);

    // ---- Layer 2: agg slices (bufB) -> expand(g_expA) -> GEMM2 -> bufA ----
    for (int sl = 0; sl < 2; ++sl)
        agg_slice_kernel<true, false, false><<<NN, 128>>>(nullptr, 1, 256,
                                                          nullptr, -1, nullptr, sl * 128);
    gemm_bf16<true, true, false><<<dim3(8, gM), 256, GK_SMEM>>>(
        0, EXPW2_OFF, b2, nullptr, 0, 0, NN, 768, 1024);

    // ---- Layer 3: agg slices (bufA) -> expand(g_expA) -> GEMM3 -> g_expB ---
    for (int sl = 0; sl < 8; ++sl)
        agg_slice_kernel<true, false, false><<<NN, 128>>>(nullptr, 0, 1024,
                                                          nullptr, -1, nullptr, sl * 128);
    gemm_bf16<true, true, true><<<dim3(8, gM), 256, GK_SMEM>>>(
        0, EXPW3_OFF, b3, nullptr, -1, 1, NN, 3072, 1024);

    // ---- Layer 4: GEMM4 (g_expB) -> bufA ; agg slices + b4 + relu -> bufB --
    gemm_bf16<false, false, false><<<dim3(2, gM), 256, GK_SMEM>>>(
        1, EXPW4_OFF, nullptr, nullptr, 0, 0, NN, 3072, 256);
    for (int sl = 0; sl < 2; ++sl)
        agg_slice_kernel<false, true, true><<<NN, 128>>>(nullptr, 0, 256,
                                                         nullptr, 1, b4, sl * 128);

    // ---- Layer 5: GEMM 256x6 (bufB -> bufA) -> agg [F=6] + b5 -> out ----
    gemm6_kernel<<<gWarp, TPB>>>(W5);
    agg_warp_kernel<6, false, false, true><<<gWarp, TPB>>>(nullptr, 0, out, -1, b5);
}

// round 14
// speedup vs baseline: 2.1158x; 1.4084x over previous
#include <cuda_runtime.h>
#include <cuda_fp16.h>
#include <cstdint>
#include <cstddef>

#define NN 100000
#define MAXE 3300000

// ---------------- scratch ----------------
__device__ int   g_deg[NN];
__device__ float g_dinv[NN];
__device__ int   g_rowptr[NN + 1];
__device__ int   g_cursor[NN];
__device__ int   g_col[MAXE];
__device__ __align__(16) float g_bufA[(size_t)NN * 1024];
__device__ __align__(16) float g_bufB[(size_t)NN * 1024];
// expanded fp16 activations (A-slots: hi, lo), max row = 2*1024
__device__ __align__(16) __half g_expA[(size_t)NN * 2048];
__device__ __align__(16) __half g_expB[(size_t)NN * 2048];
// expanded weights (B-slots: hi, hi), layout [Nc][2K] row-major
#define EXPW1_OFF 0              // 2*32*256    = 16384
#define EXPW2_OFF 16384          // 2*256*1024  = 524288
#define EXPW3_OFF 540672         // 2*1024*1024 = 2097152
#define EXPW4_OFF 2637824        // 2*1024*256  = 524288
#define EXPW_TOT  3162112
__device__ __align__(16) __half g_expW[EXPW_TOT];

// ---- ALL global-scratch pointers resolved ON DEVICE via selectors ----
__device__ __forceinline__ const float* rbuf(const float* p, int sel) {
    if (sel == 0) return g_bufA;
    if (sel == 1) return g_bufB;
    return p;
}
__device__ __forceinline__ float* wbuf(float* p, int sel) {
    if (sel == 0) return g_bufA;
    if (sel == 1) return g_bufB;
    return p;
}
__device__ __forceinline__ const __half* rexp(int sel) {
    return sel ? g_expB : g_expA;
}
__device__ __forceinline__ __half* wexp(int sel) {
    return sel ? g_expB : g_expA;
}

__device__ __forceinline__ uint32_t smem_u32(const void* p) {
    uint32_t a;
    asm("{ .reg .u64 t; cvta.to.shared.u64 t, %1; cvt.u32.u64 %0, t; }"
        : "=r"(a) : "l"(p));
    return a;
}

// A-slot pair (hi, lo): x represented exactly across two fp16 slots
__device__ __forceinline__ void wexpA(__half* p, float x) {
    __half h = __float2half_rn(x);
    __half l = __float2half_rn(x - __half2float(h));
    p[0] = h; p[1] = l;
}

// ---------------- weight expansion: B'[n][2k+s] = (hi, hi) -----------------
__global__ void k_expand_w(const float* __restrict__ W, int K, int Nc, int off) {
    int t = blockIdx.x * blockDim.x + threadIdx.x;
    if (t >= K * Nc) return;
    int n = t / K, k = t - n * K;
    float x = W[(size_t)k * Nc + n];
    __half h = __float2half_rn(x);
    __half* p = g_expW + off + (size_t)n * (2 * K) + 2 * k;
    p[0] = h; p[1] = h;
}

// ---------------- CSR construction ----------------
__global__ void k_init_deg() {
    int v = blockIdx.x * blockDim.x + threadIdx.x;
    if (v < NN) g_deg[v] = 1;
}
__global__ void k_count(const int* __restrict__ ei, int E) {
    int i = blockIdx.x * blockDim.x + threadIdx.x;
    if (i < E) {
        int d = ei[E + i];
        if ((unsigned)d < NN) atomicAdd(&g_deg[d], 1);
    }
}
__global__ void k_scan() {
    __shared__ int s[1024];
    int tid = threadIdx.x;
    int carry = 0;
    if (tid == 0) g_rowptr[0] = 0;
    for (int base = 0; base < NN; base += 1024) {
        int idx = base + tid;
        int v = (idx < NN) ? g_deg[idx] : 0;
        __syncthreads();
        s[tid] = v;
        __syncthreads();
        for (int off = 1; off < 1024; off <<= 1) {
            int t = (tid >= off) ? s[tid - off] : 0;
            __syncthreads();
            s[tid] += t;
            __syncthreads();
        }
        int incl = s[tid];
        if (idx < NN) {
            g_rowptr[idx + 1] = carry + incl;
            g_cursor[idx]     = carry + incl - v;
        }
        carry += s[1023];
        __syncthreads();
    }
}
__global__ void k_node_prep() {
    int v = blockIdx.x * blockDim.x + threadIdx.x;
    if (v < NN) {
        g_dinv[v] = rsqrtf((float)g_deg[v]);
        int pos = atomicAdd(&g_cursor[v], 1);
        if ((unsigned)pos < MAXE) g_col[pos] = v;
    }
}
__global__ void k_fill_edges(const int* __restrict__ ei, int E) {
    int i = blockIdx.x * blockDim.x + threadIdx.x;
    if (i < E) {
        int srcv = ei[i];
        int dstv = ei[E + i];
        if ((unsigned)srcv < NN && (unsigned)dstv < NN) {
            int pos = atomicAdd(&g_cursor[dstv], 1);
            if ((unsigned)pos < MAXE) g_col[pos] = srcv;
        }
    }
}

// ---------------- aggregation ----------------
template <int F, bool EXPAND, bool RELU, bool BIAS>
__global__ void agg_warp_kernel(const float* inp, int insel,
                                float* outp, int outsel,
                                const float* __restrict__ bias) {
    const float* in = rbuf(inp, insel);
    int gt = blockIdx.x * blockDim.x + threadIdx.x;
    int v = gt >> 5;
    int lane = gt & 31;
    if (v >= NN || lane >= F) return;
    float acc = 0.0f;
    int s = g_rowptr[v], e = g_rowptr[v + 1];
    for (int p = s; p < e; ++p) {
        int u = g_col[p];
        acc = fmaf(g_dinv[u], in[(size_t)u * F + lane], acc);
    }
    float val = acc * g_dinv[v];
    if (BIAS) val += bias[lane];
    if (RELU) val = fmaxf(val, 0.0f);
    if (EXPAND) {
        wexpA(g_expA + (size_t)v * (2 * F) + 2 * lane, val);
    } else {
        wbuf(outp, outsel)[(size_t)v * F + lane] = val;
    }
}

template <bool EXPAND, bool RELU, bool BIAS>
__global__ void agg_slice_kernel(const float* inp, int insel, int Ftot,
                                 float* outp, int outsel,
                                 const float* __restrict__ bias, int coloff) {
    const float* in = rbuf(inp, insel);
    int v = blockIdx.x;
    int tid = threadIdx.x;           // blockDim = 128
    int col = coloff + tid;
    float acc = 0.0f;
    int s = g_rowptr[v], e = g_rowptr[v + 1];
    const float* base = in + col;
    for (int p = s; p < e; ++p) {
        int u = g_col[p];
        acc = fmaf(g_dinv[u], base[(size_t)u * Ftot], acc);
    }
    float val = acc * g_dinv[v];
    if (BIAS) val += bias[col];
    if (RELU) val = fmaxf(val, 0.0f);
    if (EXPAND) {
        wexpA(g_expA + (size_t)v * (2 * Ftot) + 2 * col, val);
    } else {
        wbuf(outp, outsel)[(size_t)v * Ftot + col] = val;
    }
}

// ================= fp16 mma.sync GEMM, ldmatrix + 4-stage cp.async =========
// C[M,Nc] = A'[M,K2] @ B'[Nc,K2]^T  (K2 = 2K, fp16 2-slot split)
// CTA tile 128m x 128n; 8 warps each 64x32; chunk 32 k'; 4-stage pipeline,
// one __syncthreads per chunk. Rows padded to 40 fp16 (80B = 20 words):
// ldmatrix 8-row starts at words 20r mod 32 -> spans tile all 32 banks.

#define GK_CH    32
#define GK_STR   40
#define GK_HALF  (128 * GK_STR * 2)       // 10240 B per operand per stage
#define GK_STAGE (2 * GK_HALF)            // 20480 B
#define GK_NST   4
#define GK_SMEM  (GK_NST * GK_STAGE)      // 81920 B

__device__ __forceinline__ void mma16816(float* c, const uint32_t* a, const uint32_t* b) {
    asm volatile(
        "mma.sync.aligned.m16n8k16.row.col.f32.f16.f16.f32 "
        "{%0,%1,%2,%3}, {%4,%5,%6,%7}, {%8,%9}, {%0,%1,%2,%3};"
        : "+f"(c[0]), "+f"(c[1]), "+f"(c[2]), "+f"(c[3])
        : "r"(a[0]), "r"(a[1]), "r"(a[2]), "r"(a[3]), "r"(b[0]), "r"(b[1]));
}

__device__ __forceinline__ void ldsm_x4(uint32_t* r, uint32_t addr) {
    asm volatile("ldmatrix.sync.aligned.m8n8.x4.shared.b16 {%0,%1,%2,%3}, [%4];"
        : "=r"(r[0]), "=r"(r[1]), "=r"(r[2]), "=r"(r[3]) : "r"(addr));
}

__device__ __forceinline__ void gk_stage(const __half* __restrict__ Aexp,
                                         const __half* __restrict__ Bexp,
                                         char* smem_base, int c,
                                         int bm, int bn, int M, int K2, int tid) {
    char* st = smem_base + (c % GK_NST) * GK_STAGE;
    __half* Ab = (__half*)st;
    __half* Bb = (__half*)(st + GK_HALF);
    const int k0 = c * GK_CH;
#pragma unroll
    for (int i = 0; i < 4; ++i) {
        int cid = tid + i * 256;                 // 0..1023
        int isB = cid >= 512;
        int local = cid & 511;
        int row = local >> 2;
        int seg = local & 3;
        const __half* src;
        uint32_t dst;
        int nb = 16;
        if (isB) {
            src = Bexp + (size_t)(bn + row) * K2 + k0 + seg * 8;
            dst = smem_u32(Bb + row * GK_STR + seg * 8);
        } else {
            int gm = bm + row;
            if (gm >= M) gm = 0;                 // keep src in-bounds
            src = Aexp + (size_t)gm * K2 + k0 + seg * 8;
            dst = smem_u32(Ab + row * GK_STR + seg * 8);
            if (bm + row >= M) nb = 0;           // zero-fill OOB rows
        }
        asm volatile("cp.async.cg.shared.global [%0], [%1], 16, %2;"
                     :: "r"(dst), "l"(src), "r"(nb));
    }
    asm volatile("cp.async.commit_group;");
}

// write expanded pairs (next layer's A-slots) for two adjacent columns
__device__ __forceinline__ void wexpA2(__half* p, float a, float b) {
    __half h0 = __float2half_rn(a);
    __half l0 = __float2half_rn(a - __half2float(h0));
    __half h1 = __float2half_rn(b);
    __half l1 = __float2half_rn(b - __half2float(h1));
    p[0] = h0; p[1] = l0; p[2] = h1; p[3] = l1;
}

// aexp_sel: 0->g_expA, 1->g_expB ; woff: offset into g_expW
template <bool RELU, bool BIAS, bool EXPOUT>
__global__ __launch_bounds__(256, 2)
void gemm_f16(int aexp_sel, int woff,
              const float* __restrict__ bias,
              float* Cp, int csel, int eout_sel,
              int M, int K2, int Nc) {
    extern __shared__ __align__(16) char smem_raw[];
    const __half* Aexp = rexp(aexp_sel);
    const __half* Bexp = g_expW + woff;
    __half* EOut = wexp(eout_sel);
    float* C = wbuf(Cp, csel);
    const int tid = threadIdx.x;
    const int wid = tid >> 5, lane = tid & 31;
    const int g = lane >> 2, tg = lane & 3;
    const int bn = blockIdx.x * 128;   // N fastest: consecutive CTAs share A in L2
    const int bm = blockIdx.y * 128;
    const int wm = (wid & 1) * 64, wn = (wid >> 1) * 32;

    // ldmatrix lane-offsets (element units)
    const int a_mlane = ((lane >> 3) & 1) * 8 + (lane & 7);   // m within 16
    const int a_klane = ((lane >> 4) & 1) * 8;                // k half
    const int b_nlane = ((lane >> 4) & 1) * 8 + (lane & 7);   // n within 16
    const int b_klane = ((lane >> 3) & 1) * 8;                // k half

    float acc[4][4][4];
#pragma unroll
    for (int i = 0; i < 4; ++i)
#pragma unroll
        for (int j = 0; j < 4; ++j)
#pragma unroll
            for (int q = 0; q < 4; ++q) acc[i][j][q] = 0.0f;

    const int nch = K2 / GK_CH;
    gk_stage(Aexp, Bexp, smem_raw, 0, bm, bn, M, K2, tid);
    if (nch > 1) gk_stage(Aexp, Bexp, smem_raw, 1, bm, bn, M, K2, tid);
    if (nch > 2) gk_stage(Aexp, Bexp, smem_raw, 2, bm, bn, M, K2, tid);

    for (int c = 0; c < nch; ++c) {
        const int rem = nch - 1 - c;               // stages still to consume after this
        if (rem >= 2)      asm volatile("cp.async.wait_group 2;");
        else if (rem == 1) asm volatile("cp.async.wait_group 1;");
        else               asm volatile("cp.async.wait_group 0;");
        __syncthreads();
        if (c + 3 < nch)
            gk_stage(Aexp, Bexp, smem_raw, c + 3, bm, bn, M, K2, tid);

        char* st = smem_raw + (c % GK_NST) * GK_STAGE;
        const uint32_t sA = smem_u32(st);
        const uint32_t sB = sA + GK_HALF;
        const uint32_t aBase = sA + 2u * ((wm + a_mlane) * GK_STR + a_klane);
        const uint32_t bBase = sB + 2u * ((wn + b_nlane) * GK_STR + b_klane);
#pragma unroll
        for (int ks = 0; ks < 2; ++ks) {
            const int kb2 = ks * 32;               // ks*16 elems * 2 bytes
            uint32_t af[4][4], bf[4][2];
#pragma unroll
            for (int i = 0; i < 4; ++i)
                ldsm_x4(af[i], aBase + (uint32_t)(i * 16 * GK_STR * 2) + kb2);
#pragma unroll
            for (int p = 0; p < 2; ++p) {
                uint32_t r[4];
                ldsm_x4(r, bBase + (uint32_t)(p * 16 * GK_STR * 2) + kb2);
                bf[2 * p][0] = r[0]; bf[2 * p][1] = r[1];
                bf[2 * p + 1][0] = r[2]; bf[2 * p + 1][1] = r[3];
            }
#pragma unroll
            for (int i = 0; i < 4; ++i)
#pragma unroll
                for (int j = 0; j < 4; ++j)
                    mma16816(acc[i][j], af[i], bf[j]);
        }
        __syncthreads();
    }

    // epilogue
#pragma unroll
    for (int i = 0; i < 4; ++i) {
        const int r0 = bm + wm + i * 16 + g;
#pragma unroll
        for (int j = 0; j < 4; ++j) {
            const int col = bn + wn + j * 8 + 2 * tg;
            float v0 = acc[i][j][0], v1 = acc[i][j][1];
            float v2 = acc[i][j][2], v3 = acc[i][j][3];
            if (BIAS) {
                float bb0 = bias[col], bb1 = bias[col + 1];
                v0 += bb0; v1 += bb1; v2 += bb0; v3 += bb1;
            }
            if (RELU) {
                v0 = fmaxf(v0, 0.0f); v1 = fmaxf(v1, 0.0f);
                v2 = fmaxf(v2, 0.0f); v3 = fmaxf(v3, 0.0f);
            }
            if (EXPOUT) {
                if (r0 < M)
                    wexpA2(EOut + (size_t)r0 * (2 * Nc) + 2 * col, v0, v1);
                if (r0 + 8 < M)
                    wexpA2(EOut + (size_t)(r0 + 8) * (2 * Nc) + 2 * col, v2, v3);
            } else {
                if (r0 < M)
                    *(float2*)(C + (size_t)r0 * Nc + col) = make_float2(v0, v1);
                if (r0 + 8 < M)
                    *(float2*)(C + (size_t)(r0 + 8) * Nc + col) = make_float2(v2, v3);
            }
        }
    }
}

// ---------------- tiny GEMM for final layer: [NN,256] @ [256,6] ----------
__global__ void gemm6_kernel(const float* __restrict__ W) {
    const float* A = g_bufB;
    float*       C = g_bufA;
    int gt = blockIdx.x * blockDim.x + threadIdx.x;
    int row = gt >> 5;
    int lane = gt & 31;
    if (row >= NN) return;
    float acc[6] = {0.f, 0.f, 0.f, 0.f, 0.f, 0.f};
    const float* a = A + (size_t)row * 256;
    for (int k = lane; k < 256; k += 32) {
        float av = a[k];
        const float* wr = W + k * 6;
#pragma unroll
        for (int j = 0; j < 6; ++j) acc[j] = fmaf(av, wr[j], acc[j]);
    }
#pragma unroll
    for (int j = 0; j < 6; ++j)
#pragma unroll
        for (int off = 16; off > 0; off >>= 1)
            acc[j] += __shfl_xor_sync(0xFFFFFFFFu, acc[j], off);
    if (lane < 6) C[(size_t)row * 6 + lane] = acc[lane];
}

// ---------------- host pipeline ----------------
extern "C" void kernel_launch(void* const* d_in, const int* in_sizes, int n_in,
                              void* d_out, int out_size) {
    const float* x  = (const float*)d_in[0];
    const int*   ei = (const int*)d_in[1];
    const float* W1 = (const float*)d_in[2];
    const float* b1 = (const float*)d_in[3];
    const float* W2 = (const float*)d_in[4];
    const float* b2 = (const float*)d_in[5];
    const float* W3 = (const float*)d_in[6];
    const float* b3 = (const float*)d_in[7];
    const float* W4 = (const float*)d_in[8];
    const float* b4 = (const float*)d_in[9];
    const float* W5 = (const float*)d_in[10];
    const float* b5 = (const float*)d_in[11];
    float* out = (float*)d_out;

    const int E = in_sizes[1] / 2;

    cudaFuncSetAttribute(gemm_f16<true, true, false>,
                         cudaFuncAttributeMaxDynamicSharedMemorySize, GK_SMEM);
    cudaFuncSetAttribute(gemm_f16<true, true, true>,
                         cudaFuncAttributeMaxDynamicSharedMemorySize, GK_SMEM);
    cudaFuncSetAttribute(gemm_f16<false, false, false>,
                         cudaFuncAttributeMaxDynamicSharedMemorySize, GK_SMEM);

    const int TPB = 256;
    const int gN = (NN + TPB - 1) / TPB;
    const int gE = (E + TPB - 1) / TPB;
    const int gWarp = ((NN * 32) + TPB - 1) / TPB;
    const int gM = (NN + 127) / 128;   // 782

    // ---- CSR + norm ----
    k_init_deg<<<gN, TPB>>>();
    k_count<<<gE, TPB>>>(ei, E);
    k_scan<<<1, 1024>>>();
    k_node_prep<<<gN, TPB>>>();
    k_fill_edges<<<gE, TPB>>>(ei, E);

    // ---- expand weights (B-slots hi,hi) ----
    k_expand_w<<<(32 * 256 + 255) / 256, 256>>>(W1, 32, 256, EXPW1_OFF);
    k_expand_w<<<(256 * 1024 + 255) / 256, 256>>>(W2, 256, 1024, EXPW2_OFF);
    k_expand_w<<<(1024 * 1024 + 255) / 256, 256>>>(W3, 1024, 1024, EXPW3_OFF);
    k_expand_w<<<(1024 * 256 + 255) / 256, 256>>>(W4, 1024, 256, EXPW4_OFF);

    // ---- Layer 1: agg(x) [F=32] -> expand(g_expA) -> GEMM1 -> bufB ----
    agg_warp_kernel<32, true, false, false><<<gWarp, TPB>>>(x, -1, nullptr, -1, nullptr);
    gemm_f16<true, true, false><<<dim3(2, gM), 256, GK_SMEM>>>(
        0, EXPW1_OFF, b1, nullptr, 1, 0, NN, 64, 256);

    // ---- Layer 2: agg slices (bufB) -> expand(g_expA) -> GEMM2 -> bufA ----
    for (int sl = 0; sl < 2; ++sl)
        agg_slice_kernel<true, false, false><<<NN, 128>>>(nullptr, 1, 256,
                                                          nullptr, -1, nullptr, sl * 128);
    gemm_f16<true, true, false><<<dim3(8, gM), 256, GK_SMEM>>>(
        0, EXPW2_OFF, b2, nullptr, 0, 0, NN, 512, 1024);

    // ---- Layer 3: agg slices (bufA) -> expand(g_expA) -> GEMM3 -> g_expB ---
    for (int sl = 0; sl < 8; ++sl)
        agg_slice_kernel<true, false, false><<<NN, 128>>>(nullptr, 0, 1024,
                                                          nullptr, -1, nullptr, sl * 128);
    gemm_f16<true, true, true><<<dim3(8, gM), 256, GK_SMEM>>>(
        0, EXPW3_OFF, b3, nullptr, -1, 1, NN, 2048, 1024);

    // ---- Layer 4: GEMM4 (g_expB) -> bufA ; agg slices + b4 + relu -> bufB --
    gemm_f16<false, false, false><<<dim3(2, gM), 256, GK_SMEM>>>(
        1, EXPW4_OFF, nullptr, nullptr, 0, 0, NN, 2048, 256);
    for (int sl = 0; sl < 2; ++sl)
        agg_slice_kernel<false, true, true><<<NN, 128>>>(nullptr, 0, 256,
                                                         nullptr, 1, b4, sl * 128);

    // ---- Layer 5: GEMM 256x6 (bufB -> bufA) -> agg [F=6] + b5 -> out ----
    gemm6_kernel<<<gWarp, TPB>>>(W5);
    agg_warp_kernel<6, false, false, true><<<gWarp, TPB>>>(nullptr, 0, out, -1, b5);
}

// round 15
// speedup vs baseline: 3.3882x; 1.6014x over previous
#include <cuda_runtime.h>
#include <cuda_fp16.h>
#include <cstdint>
#include <cstddef>

#define NN 100000
#define MAXE 3300000

// ---------------- scratch ----------------
__device__ int   g_deg[NN];
__device__ float g_dinv[NN];
__device__ int   g_rowptr[NN + 1];
__device__ int   g_cursor[NN];
__device__ int   g_col[MAXE];
__device__ __align__(16) float g_bufA[(size_t)NN * 1024];
__device__ __align__(16) float g_bufB[(size_t)NN * 1024];
// fp16 activation ping-pong buffers (plain fp16, row stride = layer F)
__device__ __align__(16) __half g_expA[(size_t)NN * 2048];
__device__ __align__(16) __half g_expB[(size_t)NN * 2048];
// fp16 weights, transposed: layout [Nc][K] row-major
#define EXPW1_OFF 0              // 32*256    = 8192
#define EXPW2_OFF 8192           // 256*1024  = 262144
#define EXPW3_OFF 270336         // 1024*1024 = 1048576
#define EXPW4_OFF 1318912        // 1024*256  = 262144
#define EXPW_TOT  1581056
__device__ __align__(16) __half g_expW[EXPW_TOT];

// ---- ALL global-scratch pointers resolved ON DEVICE via selectors ----
__device__ __forceinline__ const float* rbuf(const float* p, int sel) {
    if (sel == 0) return g_bufA;
    if (sel == 1) return g_bufB;
    return p;
}
__device__ __forceinline__ float* wbuf(float* p, int sel) {
    if (sel == 0) return g_bufA;
    if (sel == 1) return g_bufB;
    return p;
}
__device__ __forceinline__ const __half* rexp(int sel) {
    return sel ? g_expB : g_expA;
}
__device__ __forceinline__ __half* wexp(int sel) {
    return sel ? g_expB : g_expA;
}

__device__ __forceinline__ uint32_t smem_u32(const void* p) {
    uint32_t a;
    asm("{ .reg .u64 t; cvta.to.shared.u64 t, %1; cvt.u32.u64 %0, t; }"
        : "=r"(a) : "l"(p));
    return a;
}

// ---------------- weight conversion: W16[n][k] = fp16(W[k][n]) -------------
__global__ void k_expand_w(const float* __restrict__ W, int K, int Nc, int off) {
    int t = blockIdx.x * blockDim.x + threadIdx.x;
    if (t >= K * Nc) return;
    int n = t / K, k = t - n * K;
    g_expW[off + (size_t)n * K + k] = __float2half_rn(W[(size_t)k * Nc + n]);
}

// ---------------- CSR construction ----------------
__global__ void k_init_deg() {
    int v = blockIdx.x * blockDim.x + threadIdx.x;
    if (v < NN) g_deg[v] = 1;
}
__global__ void k_count(const int* __restrict__ ei, int E) {
    int i = blockIdx.x * blockDim.x + threadIdx.x;
    if (i < E) {
        int d = ei[E + i];
        if ((unsigned)d < NN) atomicAdd(&g_deg[d], 1);
    }
}
__global__ void k_scan() {
    __shared__ int s[1024];
    int tid = threadIdx.x;
    int carry = 0;
    if (tid == 0) g_rowptr[0] = 0;
    for (int base = 0; base < NN; base += 1024) {
        int idx = base + tid;
        int v = (idx < NN) ? g_deg[idx] : 0;
        __syncthreads();
        s[tid] = v;
        __syncthreads();
        for (int off = 1; off < 1024; off <<= 1) {
            int t = (tid >= off) ? s[tid - off] : 0;
            __syncthreads();
            s[tid] += t;
            __syncthreads();
        }
        int incl = s[tid];
        if (idx < NN) {
            g_rowptr[idx + 1] = carry + incl;
            g_cursor[idx]     = carry + incl - v;
        }
        carry += s[1023];
        __syncthreads();
    }
}
__global__ void k_node_prep() {
    int v = blockIdx.x * blockDim.x + threadIdx.x;
    if (v < NN) {
        g_dinv[v] = rsqrtf((float)g_deg[v]);
        int pos = atomicAdd(&g_cursor[v], 1);
        if ((unsigned)pos < MAXE) g_col[pos] = v;
    }
}
__global__ void k_fill_edges(const int* __restrict__ ei, int E) {
    int i = blockIdx.x * blockDim.x + threadIdx.x;
    if (i < E) {
        int srcv = ei[i];
        int dstv = ei[E + i];
        if ((unsigned)srcv < NN && (unsigned)dstv < NN) {
            int pos = atomicAdd(&g_cursor[dstv], 1);
            if ((unsigned)pos < MAXE) g_col[pos] = srcv;
        }
    }
}

// ---------------- aggregation ----------------
// warp-per-node, fp32 in; OUT16: write fp16 (for GEMM A), else fp32
template <int F, bool OUT16, bool RELU, bool BIAS>
__global__ void agg_warp_kernel(const float* inp, int insel,
                                float* outp, int outsel, int o16sel,
                                const float* __restrict__ bias) {
    const float* in = rbuf(inp, insel);
    int gt = blockIdx.x * blockDim.x + threadIdx.x;
    int v = gt >> 5;
    int lane = gt & 31;
    if (v >= NN || lane >= F) return;
    float acc = 0.0f;
    int s = g_rowptr[v], e = g_rowptr[v + 1];
    for (int p = s; p < e; ++p) {
        int u = g_col[p];
        acc = fmaf(g_dinv[u], in[(size_t)u * F + lane], acc);
    }
    float val = acc * g_dinv[v];
    if (BIAS) val += bias[lane];
    if (RELU) val = fmaxf(val, 0.0f);
    if (OUT16) {
        wexp(o16sel)[(size_t)v * F + lane] = __float2half_rn(val);
    } else {
        wbuf(outp, outsel)[(size_t)v * F + lane] = val;
    }
}

// fp16 gather slice: 256 cols per pass (128 threads x half2), fp16 out
__global__ void agg_f16_slice(int insel, int outsel, int Ftot, int coloff) {
    const __half* in = rexp(insel);
    __half* out = wexp(outsel);
    int v = blockIdx.x;
    int col = coloff + 2 * threadIdx.x;
    float ax = 0.0f, ay = 0.0f;
    int s = g_rowptr[v], e = g_rowptr[v + 1];
    const __half* base = in + col;
    for (int p = s; p < e; ++p) {
        int u = g_col[p];
        float du = g_dinv[u];
        __half2 hv = *(const __half2*)(base + (size_t)u * Ftot);
        float2 f = __half22float2(hv);
        ax = fmaf(du, f.x, ax);
        ay = fmaf(du, f.y, ay);
    }
    float dv = g_dinv[v];
    *(__half2*)(out + (size_t)v * Ftot + col) = __floats2half2_rn(ax * dv, ay * dv);
}

// fp32 gather slice (128 cols), fp32 out (+bias/relu) — used after GEMM4
template <bool RELU, bool BIAS>
__global__ void agg_slice_kernel(const float* inp, int insel, int Ftot,
                                 float* outp, int outsel,
                                 const float* __restrict__ bias, int coloff) {
    const float* in = rbuf(inp, insel);
    int v = blockIdx.x;
    int tid = threadIdx.x;           // blockDim = 128
    int col = coloff + tid;
    float acc = 0.0f;
    int s = g_rowptr[v], e = g_rowptr[v + 1];
    const float* base = in + col;
    for (int p = s; p < e; ++p) {
        int u = g_col[p];
        acc = fmaf(g_dinv[u], base[(size_t)u * Ftot], acc);
    }
    float val = acc * g_dinv[v];
    if (BIAS) val += bias[col];
    if (RELU) val = fmaxf(val, 0.0f);
    wbuf(outp, outsel)[(size_t)v * Ftot + col] = val;
}

// ================= plain fp16 mma.sync GEMM, ldmatrix + 4-stage cp.async ===
// C[M,Nc] = A[M,K] @ W16[Nc,K]^T ; fp16 operands, fp32 accum.
// CTA tile 128m x 128n; 8 warps each 64x32; chunk 32 k; 4-stage pipeline.
// Rows padded to 40 fp16 (80B = 20 words): conflict-free ldmatrix.

#define GK_CH    32
#define GK_STR   40
#define GK_HALF  (128 * GK_STR * 2)       // 10240 B per operand per stage
#define GK_STAGE (2 * GK_HALF)            // 20480 B
#define GK_NST   4
#define GK_SMEM  (GK_NST * GK_STAGE)      // 81920 B

__device__ __forceinline__ void mma16816(float* c, const uint32_t* a, const uint32_t* b) {
    asm volatile(
        "mma.sync.aligned.m16n8k16.row.col.f32.f16.f16.f32 "
        "{%0,%1,%2,%3}, {%4,%5,%6,%7}, {%8,%9}, {%0,%1,%2,%3};"
        : "+f"(c[0]), "+f"(c[1]), "+f"(c[2]), "+f"(c[3])
        : "r"(a[0]), "r"(a[1]), "r"(a[2]), "r"(a[3]), "r"(b[0]), "r"(b[1]));
}

__device__ __forceinline__ void ldsm_x4(uint32_t* r, uint32_t addr) {
    asm volatile("ldmatrix.sync.aligned.m8n8.x4.shared.b16 {%0,%1,%2,%3}, [%4];"
        : "=r"(r[0]), "=r"(r[1]), "=r"(r[2]), "=r"(r[3]) : "r"(addr));
}

__device__ __forceinline__ void gk_stage(const __half* __restrict__ Aexp,
                                         const __half* __restrict__ Bexp,
                                         char* smem_base, int c,
                                         int bm, int bn, int M, int Kd, int tid) {
    char* st = smem_base + (c % GK_NST) * GK_STAGE;
    __half* Ab = (__half*)st;
    __half* Bb = (__half*)(st + GK_HALF);
    const int k0 = c * GK_CH;
#pragma unroll
    for (int i = 0; i < 4; ++i) {
        int cid = tid + i * 256;                 // 0..1023
        int isB = cid >= 512;
        int local = cid & 511;
        int row = local >> 2;
        int seg = local & 3;
        const __half* src;
        uint32_t dst;
        int nb = 16;
        if (isB) {
            src = Bexp + (size_t)(bn + row) * Kd + k0 + seg * 8;
            dst = smem_u32(Bb + row * GK_STR + seg * 8);
        } else {
            int gm = bm + row;
            if (gm >= M) gm = 0;                 // keep src in-bounds
            src = Aexp + (size_t)gm * Kd + k0 + seg * 8;
            dst = smem_u32(Ab + row * GK_STR + seg * 8);
            if (bm + row >= M) nb = 0;           // zero-fill OOB rows
        }
        asm volatile("cp.async.cg.shared.global [%0], [%1], 16, %2;"
                     :: "r"(dst), "l"(src), "r"(nb));
    }
    asm volatile("cp.async.commit_group;");
}

// aexp_sel: 0->g_expA, 1->g_expB ; woff: offset into g_expW
// OUT16: write plain fp16 to wexp(eout_sel); else fp32 to wbuf(Cp,csel)
template <bool RELU, bool BIAS, bool OUT16>
__global__ __launch_bounds__(256, 2)
void gemm_f16(int aexp_sel, int woff,
              const float* __restrict__ bias,
              float* Cp, int csel, int eout_sel,
              int M, int Kd, int Nc) {
    extern __shared__ __align__(16) char smem_raw[];
    const __half* Aexp = rexp(aexp_sel);
    const __half* Bexp = g_expW + woff;
    __half* EOut = wexp(eout_sel);
    float* C = wbuf(Cp, csel);
    const int tid = threadIdx.x;
    const int wid = tid >> 5, lane = tid & 31;
    const int g = lane >> 2, tg = lane & 3;
    const int bn = blockIdx.x * 128;   // N fastest: consecutive CTAs share A in L2
    const int bm = blockIdx.y * 128;
    const int wm = (wid & 1) * 64, wn = (wid >> 1) * 32;

    // ldmatrix lane-offsets (element units)
    const int a_mlane = ((lane >> 3) & 1) * 8 + (lane & 7);   // m within 16
    const int a_klane = ((lane >> 4) & 1) * 8;                // k half
    const int b_nlane = ((lane >> 4) & 1) * 8 + (lane & 7);   // n within 16
    const int b_klane = ((lane >> 3) & 1) * 8;                // k half

    float acc[4][4][4];
#pragma unroll
    for (int i = 0; i < 4; ++i)
#pragma unroll
        for (int j = 0; j < 4; ++j)
#pragma unroll
            for (int q = 0; q < 4; ++q) acc[i][j][q] = 0.0f;

    const int nch = Kd / GK_CH;
    gk_stage(Aexp, Bexp, smem_raw, 0, bm, bn, M, Kd, tid);
    if (nch > 1) gk_stage(Aexp, Bexp, smem_raw, 1, bm, bn, M, Kd, tid);
    if (nch > 2) gk_stage(Aexp, Bexp, smem_raw, 2, bm, bn, M, Kd, tid);

    for (int c = 0; c < nch; ++c) {
        const int rem = nch - 1 - c;
        if (rem >= 2)      asm volatile("cp.async.wait_group 2;");
        else if (rem == 1) asm volatile("cp.async.wait_group 1;");
        else               asm volatile("cp.async.wait_group 0;");
        __syncthreads();
        if (c + 3 < nch)
            gk_stage(Aexp, Bexp, smem_raw, c + 3, bm, bn, M, Kd, tid);

        char* st = smem_raw + (c % GK_NST) * GK_STAGE;
        const uint32_t sA = smem_u32(st);
        const uint32_t sB = sA + GK_HALF;
        const uint32_t aBase = sA + 2u * ((wm + a_mlane) * GK_STR + a_klane);
        const uint32_t bBase = sB + 2u * ((wn + b_nlane) * GK_STR + b_klane);
#pragma unroll
        for (int ks = 0; ks < 2; ++ks) {
            const int kb2 = ks * 32;               // ks*16 elems * 2 bytes
            uint32_t af[4][4], bf[4][2];
#pragma unroll
            for (int i = 0; i < 4; ++i)
                ldsm_x4(af[i], aBase + (uint32_t)(i * 16 * GK_STR * 2) + kb2);
#pragma unroll
            for (int p = 0; p < 2; ++p) {
                uint32_t r[4];
                ldsm_x4(r, bBase + (uint32_t)(p * 16 * GK_STR * 2) + kb2);
                bf[2 * p][0] = r[0]; bf[2 * p][1] = r[1];
                bf[2 * p + 1][0] = r[2]; bf[2 * p + 1][1] = r[3];
            }
#pragma unroll
            for (int i = 0; i < 4; ++i)
#pragma unroll
                for (int j = 0; j < 4; ++j)
                    mma16816(acc[i][j], af[i], bf[j]);
        }
        __syncthreads();
    }

    // epilogue
#pragma unroll
    for (int i = 0; i < 4; ++i) {
        const int r0 = bm + wm + i * 16 + g;
#pragma unroll
        for (int j = 0; j < 4; ++j) {
            const int col = bn + wn + j * 8 + 2 * tg;
            float v0 = acc[i][j][0], v1 = acc[i][j][1];
            float v2 = acc[i][j][2], v3 = acc[i][j][3];
            if (BIAS) {
                float bb0 = bias[col], bb1 = bias[col + 1];
                v0 += bb0; v1 += bb1; v2 += bb0; v3 += bb1;
            }
            if (RELU) {
                v0 = fmaxf(v0, 0.0f); v1 = fmaxf(v1, 0.0f);
                v2 = fmaxf(v2, 0.0f); v3 = fmaxf(v3, 0.0f);
            }
            if (OUT16) {
                if (r0 < M)
                    *(__half2*)(EOut + (size_t)r0 * Nc + col) = __floats2half2_rn(v0, v1);
                if (r0 + 8 < M)
                    *(__half2*)(EOut + (size_t)(r0 + 8) * Nc + col) = __floats2half2_rn(v2, v3);
            } else {
                if (r0 < M)
                    *(float2*)(C + (size_t)r0 * Nc + col) = make_float2(v0, v1);
                if (r0 + 8 < M)
                    *(float2*)(C + (size_t)(r0 + 8) * Nc + col) = make_float2(v2, v3);
            }
        }
    }
}

// ---------------- tiny GEMM for final layer: [NN,256] @ [256,6] ----------
__global__ void gemm6_kernel(const float* __restrict__ W) {
    const float* A = g_bufB;
    float*       C = g_bufA;
    int gt = blockIdx.x * blockDim.x + threadIdx.x;
    int row = gt >> 5;
    int lane = gt & 31;
    if (row >= NN) return;
    float acc[6] = {0.f, 0.f, 0.f, 0.f, 0.f, 0.f};
    const float* a = A + (size_t)row * 256;
    for (int k = lane; k < 256; k += 32) {
        float av = a[k];
        const float* wr = W + k * 6;
#pragma unroll
        for (int j = 0; j < 6; ++j) acc[j] = fmaf(av, wr[j], acc[j]);
    }
#pragma unroll
    for (int j = 0; j < 6; ++j)
#pragma unroll
        for (int off = 16; off > 0; off >>= 1)
            acc[j] += __shfl_xor_sync(0xFFFFFFFFu, acc[j], off);
    if (lane < 6) C[(size_t)row * 6 + lane] = acc[lane];
}

// ---------------- host pipeline ----------------
extern "C" void kernel_launch(void* const* d_in, const int* in_sizes, int n_in,
                              void* d_out, int out_size) {
    const float* x  = (const float*)d_in[0];
    const int*   ei = (const int*)d_in[1];
    const float* W1 = (const float*)d_in[2];
    const float* b1 = (const float*)d_in[3];
    const float* W2 = (const float*)d_in[4];
    const float* b2 = (const float*)d_in[5];
    const float* W3 = (const float*)d_in[6];
    const float* b3 = (const float*)d_in[7];
    const float* W4 = (const float*)d_in[8];
    const float* b4 = (const float*)d_in[9];
    const float* W5 = (const float*)d_in[10];
    const float* b5 = (const float*)d_in[11];
    float* out = (float*)d_out;

    const int E = in_sizes[1] / 2;

    cudaFuncSetAttribute(gemm_f16<true, true, true>,
                         cudaFuncAttributeMaxDynamicSharedMemorySize, GK_SMEM);
    cudaFuncSetAttribute(gemm_f16<false, false, false>,
                         cudaFuncAttributeMaxDynamicSharedMemorySize, GK_SMEM);

    const int TPB = 256;
    const int gN = (NN + TPB - 1) / TPB;
    const int gE = (E + TPB - 1) / TPB;
    const int gWarp = ((NN * 32) + TPB - 1) / TPB;
    const int gM = (NN + 127) / 128;   // 782

    // ---- CSR + norm ----
    k_init_deg<<<gN, TPB>>>();
    k_count<<<gE, TPB>>>(ei, E);
    k_scan<<<1, 1024>>>();
    k_node_prep<<<gN, TPB>>>();
    k_fill_edges<<<gE, TPB>>>(ei, E);

    // ---- fp16 transposed weights ----
    k_expand_w<<<(32 * 256 + 255) / 256, 256>>>(W1, 32, 256, EXPW1_OFF);
    k_expand_w<<<(256 * 1024 + 255) / 256, 256>>>(W2, 256, 1024, EXPW2_OFF);
    k_expand_w<<<(1024 * 1024 + 255) / 256, 256>>>(W3, 1024, 1024, EXPW3_OFF);
    k_expand_w<<<(1024 * 256 + 255) / 256, 256>>>(W4, 1024, 256, EXPW4_OFF);

    // ---- Layer 1: agg(x) [F=32, fp32 in] -> fp16 g_expA -> GEMM1 -> fp16 g_expB
    agg_warp_kernel<32, true, false, false><<<gWarp, TPB>>>(x, -1, nullptr, -1, 0, nullptr);
    gemm_f16<true, true, true><<<dim3(2, gM), 256, GK_SMEM>>>(
        0, EXPW1_OFF, b1, nullptr, -1, 1, NN, 32, 256);

    // ---- Layer 2: fp16 agg (g_expB -> g_expA) -> GEMM2 -> fp16 g_expB ----
    agg_f16_slice<<<NN, 128>>>(1, 0, 256, 0);
    gemm_f16<true, true, true><<<dim3(8, gM), 256, GK_SMEM>>>(
        0, EXPW2_OFF, b2, nullptr, -1, 1, NN, 256, 1024);

    // ---- Layer 3: fp16 agg slices (g_expB -> g_expA) -> GEMM3 -> fp16 g_expB
    for (int sl = 0; sl < 4; ++sl)
        agg_f16_slice<<<NN, 128>>>(1, 0, 1024, sl * 256);
    gemm_f16<true, true, true><<<dim3(8, gM), 256, GK_SMEM>>>(
        0, EXPW3_OFF, b3, nullptr, -1, 1, NN, 1024, 1024);

    // ---- Layer 4: GEMM4 (g_expB) -> fp32 bufA ; fp32 agg + b4 + relu -> bufB
    gemm_f16<false, false, false><<<dim3(2, gM), 256, GK_SMEM>>>(
        1, EXPW4_OFF, nullptr, nullptr, 0, 0, NN, 1024, 256);
    for (int sl = 0; sl < 2; ++sl)
        agg_slice_kernel<true, true><<<NN, 128>>>(nullptr, 0, 256,
                                                  nullptr, 1, b4, sl * 128);

    // ---- Layer 5: GEMM 256x6 (bufB -> bufA) -> agg [F=6] + b5 -> out ----
    gemm6_kernel<<<gWarp, TPB>>>(W5);
    agg_warp_kernel<6, false, false, true><<<gWarp, TPB>>>(nullptr, 0, out, -1, 0, b5);
}

// round 17
// speedup vs baseline: 3.7807x; 1.1158x over previous
#include <cuda_runtime.h>
#include <cuda_fp16.h>
#include <cstdint>
#include <cstddef>

#define NN 100000
#define MAXE 3300000
#define NBLK 391          // ceil(NN/256)

// ---------------- scratch ----------------
__device__ int   g_deg[NN];
__device__ float g_dinv[NN];
__device__ int   g_rowptr[NN + 1];
__device__ int   g_cursor[NN];
__device__ int   g_col[MAXE];
__device__ int   g_bsum[NBLK];
__device__ int   g_boff[NBLK];
__device__ __align__(16) float g_bufA[(size_t)NN * 1024];
__device__ __align__(16) float g_bufB[(size_t)NN * 1024];
// fp16 activation ping-pong buffers (plain fp16, row stride = layer F)
__device__ __align__(16) __half g_expA[(size_t)NN * 2048];
__device__ __align__(16) __half g_expB[(size_t)NN * 2048];
// fp16 weights, transposed: layout [Nc][K] row-major
#define EXPW1_OFF 0              // 32*256    = 8192
#define EXPW2_OFF 8192           // 256*1024  = 262144
#define EXPW3_OFF 270336         // 1024*1024 = 1048576
#define EXPW4_OFF 1318912       // 1024*256  = 262144
#define EXPW_TOT  1581056
__device__ __align__(16) __half g_expW[EXPW_TOT];

// ---- ALL global-scratch pointers resolved ON DEVICE via selectors ----
__device__ __forceinline__ const float* rbuf(const float* p, int sel) {
    if (sel == 0) return g_bufA;
    if (sel == 1) return g_bufB;
    return p;
}
__device__ __forceinline__ float* wbuf(float* p, int sel) {
    if (sel == 0) return g_bufA;
    if (sel == 1) return g_bufB;
    return p;
}
__device__ __forceinline__ const __half* rexp(int sel) {
    return sel ? g_expB : g_expA;
}
__device__ __forceinline__ __half* wexp(int sel) {
    return sel ? g_expB : g_expA;
}

__device__ __forceinline__ uint32_t smem_u32(const void* p) {
    uint32_t a;
    asm("{ .reg .u64 t; cvta.to.shared.u64 t, %1; cvt.u32.u64 %0, t; }"
        : "=r"(a) : "l"(p));
    return a;
}

// ---------------- weight conversion: W16[n][k] = fp16(W[k][n]) -------------
__global__ void k_expand_w(const float* __restrict__ W, int K, int Nc, int off) {
    int t = blockIdx.x * blockDim.x + threadIdx.x;
    if (t >= K * Nc) return;
    int n = t / K, k = t - n * K;
    g_expW[off + (size_t)n * K + k] = __float2half_rn(W[(size_t)k * Nc + n]);
}

// ---------------- CSR construction ----------------
__global__ void k_init_deg() {
    int v = blockIdx.x * blockDim.x + threadIdx.x;
    if (v < NN) g_deg[v] = 1;
}
__global__ void k_count(const int* __restrict__ ei, int E) {
    int i = blockIdx.x * blockDim.x + threadIdx.x;
    if (i < E) {
        int d = ei[E + i];
        if ((unsigned)d < NN) atomicAdd(&g_deg[d], 1);
    }
}

// 3-kernel scan over g_deg -> g_rowptr / g_cursor
__global__ void k_scan1() {        // NBLK blocks x 256: block-local inclusive scan
    __shared__ int s[256];
    int tid = threadIdx.x;
    int idx = blockIdx.x * 256 + tid;
    int v = (idx < NN) ? g_deg[idx] : 0;
    s[tid] = v;
    __syncthreads();
#pragma unroll
    for (int off = 1; off < 256; off <<= 1) {
        int t = (tid >= off) ? s[tid - off] : 0;
        __syncthreads();
        s[tid] += t;
        __syncthreads();
    }
    if (idx < NN) g_rowptr[idx + 1] = s[tid];   // block-local inclusive
    if (tid == 255) g_bsum[blockIdx.x] = s[255];
}
__global__ void k_scan2() {        // 1 block x 512: exclusive scan of block sums
    __shared__ int s[512];
    int tid = threadIdx.x;
    s[tid] = (tid < NBLK) ? g_bsum[tid] : 0;
    __syncthreads();
#pragma unroll
    for (int off = 1; off < 512; off <<= 1) {
        int t = (tid >= off) ? s[tid - off] : 0;
        __syncthreads();
        s[tid] += t;
        __syncthreads();
    }
    if (tid < NBLK) g_boff[tid] = s[tid] - g_bsum[tid];   // exclusive
}
__global__ void k_scan3() {        // offsets + cursor + dinv + self-loop fill
    int idx = blockIdx.x * 256 + threadIdx.x;
    if (idx == 0) g_rowptr[0] = 0;
    if (idx < NN) {
        int incl = g_rowptr[idx + 1] + g_boff[blockIdx.x];
        g_rowptr[idx + 1] = incl;
        int deg = g_deg[idx];
        int start = incl - deg;
        g_cursor[idx] = start + 1;          // reserve slot 0 for self loop
        g_col[start] = idx;                  // self loop
        g_dinv[idx] = rsqrtf((float)deg);
    }
}
__global__ void k_fill_edges(const int* __restrict__ ei, int E) {
    int i = blockIdx.x * blockDim.x + threadIdx.x;
    if (i < E) {
        int srcv = ei[i];
        int dstv = ei[E + i];
        if ((unsigned)srcv < NN && (unsigned)dstv < NN) {
            int pos = atomicAdd(&g_cursor[dstv], 1);
            if ((unsigned)pos < MAXE) g_col[pos] = srcv;
        }
    }
}

// ---------------- aggregation ----------------
// warp-per-node, fp32 in; OUT16: write fp16 (for GEMM A), else fp32
template <int F, bool OUT16, bool RELU, bool BIAS>
__global__ void agg_warp_kernel(const float* inp, int insel,
                                float* outp, int outsel, int o16sel,
                                const float* __restrict__ bias) {
    const float* in = rbuf(inp, insel);
    int gt = blockIdx.x * blockDim.x + threadIdx.x;
    int v = gt >> 5;
    int lane = gt & 31;
    if (v >= NN || lane >= F) return;
    float acc = 0.0f;
    int s = g_rowptr[v], e = g_rowptr[v + 1];
    for (int p = s; p < e; ++p) {
        int u = g_col[p];
        acc = fmaf(g_dinv[u], in[(size_t)u * F + lane], acc);
    }
    float val = acc * g_dinv[v];
    if (BIAS) val += bias[lane];
    if (RELU) val = fmaxf(val, 0.0f);
    if (OUT16) {
        wexp(o16sel)[(size_t)v * F + lane] = __float2half_rn(val);
    } else {
        wbuf(outp, outsel)[(size_t)v * F + lane] = val;
    }
}

// fp16 gather slice: 256 cols per pass (128 threads x half2), fp16 out
__global__ void agg_f16_slice(int insel, int outsel, int Ftot, int coloff) {
    const __half* in = rexp(insel);
    __half* out = wexp(outsel);
    int v = blockIdx.x;
    int col = coloff + 2 * threadIdx.x;
    float ax = 0.0f, ay = 0.0f;
    int s = g_rowptr[v], e = g_rowptr[v + 1];
    const __half* base = in + col;
    for (int p = s; p < e; ++p) {
        int u = g_col[p];
        float du = g_dinv[u];
        __half2 hv = *(const __half2*)(base + (size_t)u * Ftot);
        float2 f = __half22float2(hv);
        ax = fmaf(du, f.x, ax);
        ay = fmaf(du, f.y, ay);
    }
    float dv = g_dinv[v];
    *(__half2*)(out + (size_t)v * Ftot + col) = __floats2half2_rn(ax * dv, ay * dv);
}

// fp16 gather -> fp32 out with bias/relu (L4 path): 256 cols, 128 threads
template <bool RELU, bool BIAS>
__global__ void agg_f16_out32(int insel, float* outp, int outsel,
                              int Ftot, int coloff,
                              const float* __restrict__ bias) {
    const __half* in = rexp(insel);
    float* out = wbuf(outp, outsel);
    int v = blockIdx.x;
    int col = coloff + 2 * threadIdx.x;
    float ax = 0.0f, ay = 0.0f;
    int s = g_rowptr[v], e = g_rowptr[v + 1];
    const __half* base = in + col;
    for (int p = s; p < e; ++p) {
        int u = g_col[p];
        float du = g_dinv[u];
        __half2 hv = *(const __half2*)(base + (size_t)u * Ftot);
        float2 f = __half22float2(hv);
        ax = fmaf(du, f.x, ax);
        ay = fmaf(du, f.y, ay);
    }
    float dv = g_dinv[v];
    ax *= dv; ay *= dv;
    if (BIAS) { ax += bias[col]; ay += bias[col + 1]; }
    if (RELU) { ax = fmaxf(ax, 0.0f); ay = fmaxf(ay, 0.0f); }
    *(float2*)(out + (size_t)v * Ftot + col) = make_float2(ax, ay);
}

// ================= plain fp16 mma.sync GEMM, ldmatrix + 4-stage cp.async ===
// C[M,Nc] = A[M,K] @ W16[Nc,K]^T ; fp16 operands, fp32 accum.
// CTA tile 128m x 128n; 8 warps each 64x32; chunk 32 k; 4-stage pipeline.
// Rows padded to 40 fp16 (80B = 20 words): conflict-free ldmatrix.

#define GK_CH    32
#define GK_STR   40
#define GK_HALF  (128 * GK_STR * 2)       // 10240 B per operand per stage
#define GK_STAGE (2 * GK_HALF)            // 20480 B
#define GK_NST   4
#define GK_SMEM  (GK_NST * GK_STAGE)      // 81920 B

__device__ __forceinline__ void mma16816(float* c, const uint32_t* a, const uint32_t* b) {
    asm volatile(
        "mma.sync.aligned.m16n8k16.row.col.f32.f16.f16.f32 "
        "{%0,%1,%2,%3}, {%4,%5,%6,%7}, {%8,%9}, {%0,%1,%2,%3};"
        : "+f"(c[0]), "+f"(c[1]), "+f"(c[2]), "+f"(c[3])
        : "r"(a[0]), "r"(a[1]), "r"(a[2]), "r"(a[3]), "r"(b[0]), "r"(b[1]));
}

__device__ __forceinline__ void ldsm_x4(uint32_t* r, uint32_t addr) {
    asm volatile("ldmatrix.sync.aligned.m8n8.x4.shared.b16 {%0,%1,%2,%3}, [%4];"
        : "=r"(r[0]), "=r"(r[1]), "=r"(r[2]), "=r"(r[3]) : "r"(addr));
}

__device__ __forceinline__ void gk_stage(const __half* __restrict__ Aexp,
                                         const __half* __restrict__ Bexp,
                                         char* smem_base, int c,
                                         int bm, int bn, int M, int Kd, int tid) {
    char* st = smem_base + (c % GK_NST) * GK_STAGE;
    __half* Ab = (__half*)st;
    __half* Bb = (__half*)(st + GK_HALF);
    const int k0 = c * GK_CH;
#pragma unroll
    for (int i = 0; i < 4; ++i) {
        int cid = tid + i * 256;                 // 0..1023
        int isB = cid >= 512;
        int local = cid & 511;
        int row = local >> 2;
        int seg = local & 3;
        const __half* src;
        uint32_t dst;
        int nb = 16;
        if (isB) {
            src = Bexp + (size_t)(bn + row) * Kd + k0 + seg * 8;
            dst = smem_u32(Bb + row * GK_STR + seg * 8);
        } else {
            int gm = bm + row;
            if (gm >= M) gm = 0;                 // keep src in-bounds
            src = Aexp + (size_t)gm * Kd + k0 + seg * 8;
            dst = smem_u32(Ab + row * GK_STR + seg * 8);
            if (bm + row >= M) nb = 0;           // zero-fill OOB rows
        }
        asm volatile("cp.async.cg.shared.global [%0], [%1], 16, %2;"
                     :: "r"(dst), "l"(src), "r"(nb));
    }
    asm volatile("cp.async.commit_group;");
}

// aexp_sel: 0->g_expA, 1->g_expB ; woff: offset into g_expW
// OUT16: write plain fp16 to wexp(eout_sel); else fp32 to wbuf(Cp,csel)
template <bool RELU, bool BIAS, bool OUT16>
__global__ __launch_bounds__(256, 2)
void gemm_f16(int aexp_sel, int woff,
              const float* __restrict__ bias,
              float* Cp, int csel, int eout_sel,
              int M, int Kd, int Nc) {
    extern __shared__ __align__(16) char smem_raw[];
    const __half* Aexp = rexp(aexp_sel);
    const __half* Bexp = g_expW + woff;
    __half* EOut = wexp(eout_sel);
    float* C = wbuf(Cp, csel);
    const int tid = threadIdx.x;
    const int wid = tid >> 5, lane = tid & 31;
    const int g = lane >> 2, tg = lane & 3;
    const int bn = blockIdx.x * 128;   // N fastest: consecutive CTAs share A in L2
    const int bm = blockIdx.y * 128;
    const int wm = (wid & 1) * 64, wn = (wid >> 1) * 32;

    const int a_mlane = ((lane >> 3) & 1) * 8 + (lane & 7);
    const int a_klane = ((lane >> 4) & 1) * 8;
    const int b_nlane = ((lane >> 4) & 1) * 8 + (lane & 7);
    const int b_klane = ((lane >> 3) & 1) * 8;

    float acc[4][4][4];
#pragma unroll
    for (int i = 0; i < 4; ++i)
#pragma unroll
        for (int j = 0; j < 4; ++j)
#pragma unroll
            for (int q = 0; q < 4; ++q) acc[i][j][q] = 0.0f;

    const int nch = Kd / GK_CH;
    gk_stage(Aexp, Bexp, smem_raw, 0, bm, bn, M, Kd, tid);
    if (nch > 1) gk_stage(Aexp, Bexp, smem_raw, 1, bm, bn, M, Kd, tid);
    if (nch > 2) gk_stage(Aexp, Bexp, smem_raw, 2, bm, bn, M, Kd, tid);

    for (int c = 0; c < nch; ++c) {
        const int rem = nch - 1 - c;
        if (rem >= 2)      asm volatile("cp.async.wait_group 2;");
        else if (rem == 1) asm volatile("cp.async.wait_group 1;");
        else               asm volatile("cp.async.wait_group 0;");
        __syncthreads();
        if (c + 3 < nch)
            gk_stage(Aexp, Bexp, smem_raw, c + 3, bm, bn, M, Kd, tid);

        char* st = smem_raw + (c % GK_NST) * GK_STAGE;
        const uint32_t sA = smem_u32(st);
        const uint32_t sB = sA + GK_HALF;
        const uint32_t aBase = sA + 2u * ((wm + a_mlane) * GK_STR + a_klane);
        const uint32_t bBase = sB + 2u * ((wn + b_nlane) * GK_STR + b_klane);
#pragma unroll
        for (int ks = 0; ks < 2; ++ks) {
            const int kb2 = ks * 32;
            uint32_t af[4][4], bf[4][2];
#pragma unroll
            for (int i = 0; i < 4; ++i)
                ldsm_x4(af[i], aBase + (uint32_t)(i * 16 * GK_STR * 2) + kb2);
#pragma unroll
            for (int p = 0; p < 2; ++p) {
                uint32_t r[4];
                ldsm_x4(r, bBase + (uint32_t)(p * 16 * GK_STR * 2) + kb2);
                bf[2 * p][0] = r[0]; bf[2 * p][1] = r[1];
                bf[2 * p + 1][0] = r[2]; bf[2 * p + 1][1] = r[3];
            }
#pragma unroll
            for (int i = 0; i < 4; ++i)
#pragma unroll
                for (int j = 0; j < 4; ++j)
                    mma16816(acc[i][j], af[i], bf[j]);
        }
        __syncthreads();
    }

    // epilogue
#pragma unroll
    for (int i = 0; i < 4; ++i) {
        const int r0 = bm + wm + i * 16 + g;
#pragma unroll
        for (int j = 0; j < 4; ++j) {
            const int col = bn + wn + j * 8 + 2 * tg;
            float v0 = acc[i][j][0], v1 = acc[i][j][1];
            float v2 = acc[i][j][2], v3 = acc[i][j][3];
            if (BIAS) {
                float bb0 = bias[col], bb1 = bias[col + 1];
                v0 += bb0; v1 += bb1; v2 += bb0; v3 += bb1;
            }
            if (RELU) {
                v0 = fmaxf(v0, 0.0f); v1 = fmaxf(v1, 0.0f);
                v2 = fmaxf(v2, 0.0f); v3 = fmaxf(v3, 0.0f);
            }
            if (OUT16) {
                if (r0 < M)
                    *(__half2*)(EOut + (size_t)r0 * Nc + col) = __floats2half2_rn(v0, v1);
                if (r0 + 8 < M)
                    *(__half2*)(EOut + (size_t)(r0 + 8) * Nc + col) = __floats2half2_rn(v2, v3);
            } else {
                if (r0 < M)
                    *(float2*)(C + (size_t)r0 * Nc + col) = make_float2(v0, v1);
                if (r0 + 8 < M)
                    *(float2*)(C + (size_t)(r0 + 8) * Nc + col) = make_float2(v2, v3);
            }
        }
    }
}

// ---------------- tiny GEMM for final layer: [NN,256] @ [256,6] ----------
__global__ void gemm6_kernel(const float* __restrict__ W) {
    const float* A = g_bufB;
    float*       C = g_bufA;
    int gt = blockIdx.x * blockDim.x + threadIdx.x;
    int row = gt >> 5;
    int lane = gt & 31;
    if (row >= NN) return;
    float acc[6] = {0.f, 0.f, 0.f, 0.f, 0.f, 0.f};
    const float* a = A + (size_t)row * 256;
    for (int k = lane; k < 256; k += 32) {
        float av = a[k];
        const float* wr = W + k * 6;
#pragma unroll
        for (int j = 0; j < 6; ++j) acc[j] = fmaf(av, wr[j], acc[j]);
    }
#pragma unroll
    for (int j = 0; j < 6; ++j)
#pragma unroll
        for (int off = 16; off > 0; off >>= 1)
            acc[j] += __shfl_xor_sync(0xFFFFFFFFu, acc[j], off);
    if (lane < 6) C[(size_t)row * 6 + lane] = acc[lane];
}

// ---------------- host pipeline ----------------
extern "C" void kernel_launch(void* const* d_in, const int* in_sizes, int n_in,
                              void* d_out, int out_size) {
    const float* x  = (const float*)d_in[0];
    const int*   ei = (const int*)d_in[1];
    const float* W1 = (const float*)d_in[2];
    const float* b1 = (const float*)d_in[3];
    const float* W2 = (const float*)d_in[4];
    const float* b2 = (const float*)d_in[5];
    const float* W3 = (const float*)d_in[6];
    const float* b3 = (const float*)d_in[7];
    const float* W4 = (const float*)d_in[8];
    const float* b4 = (const float*)d_in[9];
    const float* W5 = (const float*)d_in[10];
    const float* b5 = (const float*)d_in[11];
    float* out = (float*)d_out;

    const int E = in_sizes[1] / 2;

    cudaFuncSetAttribute(gemm_f16<true, true, true>,
                         cudaFuncAttributeMaxDynamicSharedMemorySize, GK_SMEM);
    cudaFuncSetAttribute(gemm_f16<false, false, true>,
                         cudaFuncAttributeMaxDynamicSharedMemorySize, GK_SMEM);

    const int TPB = 256;
    const int gN = (NN + TPB - 1) / TPB;   // = NBLK
    const int gE = (E + TPB - 1) / TPB;
    const int gWarp = ((NN * 32) + TPB - 1) / TPB;
    const int gM = (NN + 127) / 128;   // 782

    // ---- CSR + norm (fast 3-kernel scan; scan3 fuses node-prep) ----
    k_init_deg<<<gN, TPB>>>();
    k_count<<<gE, TPB>>>(ei, E);
    k_scan1<<<NBLK, 256>>>();
    k_scan2<<<1, 512>>>();
    k_scan3<<<NBLK, 256>>>();
    k_fill_edges<<<gE, TPB>>>(ei, E);

    // ---- fp16 transposed weights ----
    k_expand_w<<<(32 * 256 + 255) / 256, 256>>>(W1, 32, 256, EXPW1_OFF);
    k_expand_w<<<(256 * 1024 + 255) / 256, 256>>>(W2, 256, 1024, EXPW2_OFF);
    k_expand_w<<<(1024 * 1024 + 255) / 256, 256>>>(W3, 1024, 1024, EXPW3_OFF);
    k_expand_w<<<(1024 * 256 + 255) / 256, 256>>>(W4, 1024, 256, EXPW4_OFF);

    // ---- Layer 1: agg(x) [F=32, fp32 in] -> fp16 g_expA -> GEMM1 -> fp16 g_expB
    agg_warp_kernel<32, true, false, false><<<gWarp, TPB>>>(x, -1, nullptr, -1, 0, nullptr);
    gemm_f16<true, true, true><<<dim3(2, gM), 256, GK_SMEM>>>(
        0, EXPW1_OFF, b1, nullptr, -1, 1, NN, 32, 256);

    // ---- Layer 2: fp16 agg (g_expB -> g_expA) -> GEMM2 -> fp16 g_expB ----
    agg_f16_slice<<<NN, 128>>>(1, 0, 256, 0);
    gemm_f16<true, true, true><<<dim3(8, gM), 256, GK_SMEM>>>(
        0, EXPW2_OFF, b2, nullptr, -1, 1, NN, 256, 1024);

    // ---- Layer 3: fp16 agg slices (g_expB -> g_expA) -> GEMM3 -> fp16 g_expB
    for (int sl = 0; sl < 4; ++sl)
        agg_f16_slice<<<NN, 128>>>(1, 0, 1024, sl * 256);
    gemm_f16<true, true, true><<<dim3(8, gM), 256, GK_SMEM>>>(
        0, EXPW3_OFF, b3, nullptr, -1, 1, NN, 1024, 1024);

    // ---- Layer 4: GEMM4 (g_expB) -> fp16 g_expA ; fp16 agg + b4 + relu -> fp32 bufB
    gemm_f16<false, false, true><<<dim3(2, gM), 256, GK_SMEM>>>(
        1, EXPW4_OFF, nullptr, nullptr, -1, 0, NN, 1024, 256);
    agg_f16_out32<true, true><<<NN, 128>>>(0, nullptr, 1, 256, 0, b4);

    // ---- Layer 5: GEMM 256x6 (bufB -> bufA) -> agg [F=6] + b5 -> out ----
    gemm6_kernel<<<gWarp, TPB>>>(W5);
    agg_warp_kernel<6, false, false, true><<<gWarp, TPB>>>(nullptr, 0, out, -1, 0, b5);
}